// round 12
// baseline (speedup 1.0000x reference)
#include <cuda_runtime.h>
#include <cuda_fp16.h>
#include <math.h>
#include <stdint.h>

#define S_LEN   2048
#define D_MODEL 4096
#define NH      32
#define NKV     8
#define HDIM    128
#define KV_D    (NKV * HDIM)           // 1024
#define ATT_SCALE 0.08838834764831843f // 128^-0.5

// ---------------- static scratch (allocation forbidden) --------------------
__device__ float g_V[S_LEN * KV_D];

__device__ __half g_xh[S_LEN * D_MODEL],  g_xl[S_LEN * D_MODEL];
__device__ __half g_wqh[D_MODEL * D_MODEL];
__device__ __half g_wkh[KV_D * D_MODEL];
__device__ __half g_wvh[KV_D * D_MODEL];
__device__ __half g_woh[D_MODEL * D_MODEL];
__device__ __half g_ah[S_LEN * D_MODEL], g_al[S_LEN * D_MODEL];

__device__ __half g_Qfh[S_LEN * D_MODEL], g_Qfl[S_LEN * D_MODEL];  // rope'd, scaled
__device__ __half g_Kfh[S_LEN * KV_D],    g_Kfl[S_LEN * KV_D];     // rope'd
__device__ __half g_Vth[KV_D * S_LEN],    g_Vtl[KV_D * S_LEN];     // [kvh*128+d][s]

// ---------------------------------------------------------------------------
__device__ __forceinline__ void cp16(uint32_t dst, const void* src) {
    asm volatile("cp.async.cg.shared.global [%0], [%1], 16;\n" :: "r"(dst), "l"(src));
}
#define LDSM4(R0, R1, R2, R3, ADDR)                                          \
    asm volatile("ldmatrix.sync.aligned.m8n8.x4.shared.b16 {%0,%1,%2,%3},[%4];" \
                 : "=r"(R0), "=r"(R1), "=r"(R2), "=r"(R3) : "r"(ADDR))
#define MMA16816(C, A, B0, B1)                                               \
    asm volatile("mma.sync.aligned.m16n8k16.row.col.f32.f16.f16.f32 "        \
                 "{%0,%1,%2,%3},{%4,%5,%6,%7},{%8,%9},{%0,%1,%2,%3};"        \
                 : "+f"((C)[0]), "+f"((C)[1]), "+f"((C)[2]), "+f"((C)[3])    \
                 : "r"((A)[0]), "r"((A)[1]), "r"((A)[2]), "r"((A)[3]),       \
                   "r"(B0), "r"(B1))

__device__ __forceinline__ __half2 split_pair(float a, float b, __half2& lo) {
    __half ah = __float2half_rn(a), bh = __float2half_rn(b);
    lo = __halves2half2(__float2half_rn(a - __half2float(ah)),
                        __float2half_rn(b - __half2float(bh)));
    return __halves2half2(ah, bh);
}

// ---------------------------------------------------------------------------
__global__ void split_h(const float* __restrict__ in,
                        __half* __restrict__ hi, __half* __restrict__ lo, int n) {
    int i = blockIdx.x * blockDim.x + threadIdx.x;
    if (i >= n) return;
    float a = in[i];
    __half h = __float2half_rn(a);
    hi[i] = h;
    lo[i] = __float2half_rn(a - __half2float(h));
}

__global__ void cvt_h(const float* __restrict__ in, __half* __restrict__ hi, int n) {
    int i = blockIdx.x * blockDim.x + threadIdx.x;
    if (i >= n) return;
    hi[i] = __float2half_rn(in[i]);
}

// ---------------------------------------------------------------------------
__global__ void transpose_split_v(const float* __restrict__ V,
                                  __half* __restrict__ Vth,
                                  __half* __restrict__ Vtl) {
    __shared__ float tile[32][33];
    const int s0 = blockIdx.x * 32, d0 = blockIdx.y * 32;
    const int tx = threadIdx.x, ty = threadIdx.y;
#pragma unroll
    for (int i = 0; i < 4; i++)
        tile[ty + 8 * i][tx] = V[(size_t)(s0 + ty + 8 * i) * KV_D + d0 + tx];
    __syncthreads();
#pragma unroll
    for (int i = 0; i < 4; i++) {
        int d = d0 + ty + 8 * i, s = s0 + tx;
        float v = tile[tx][ty + 8 * i];
        __half h = __float2half_rn(v);
        Vth[(size_t)d * S_LEN + s] = h;
        Vtl[(size_t)d * S_LEN + s] = __float2half_rn(v - __half2float(h));
    }
}

// ---------------------------------------------------------------------------
// HGEMM 2-term split: C = (Ah + Al) @ Bh^T, fp32 accum.
// MODE 0: fp32 C out. MODE 1: rope+scale+split-fp16 out.
// 128x128 tile, k32, 3-stage cp.async ring, 256 threads, 2 CTAs/SM.
// ---------------------------------------------------------------------------
#define HGEMM_SMEM (3 * 32768)

template<int MODE>
__global__ __launch_bounds__(256, 2)
void hgemm_split(const __half* __restrict__ Ah, const __half* __restrict__ Al,
                 const __half* __restrict__ Bh,
                 float* __restrict__ C,
                 __half* __restrict__ Hi, __half* __restrict__ Lo,
                 const float* __restrict__ cosw, const float* __restrict__ sinw,
                 float scale, int M, int N, int K) {
    extern __shared__ __half smh[];
    const uint32_t sbase = (uint32_t)__cvta_generic_to_shared(smh);

    const int t    = threadIdx.x;
    const int m0   = blockIdx.y * 128;
    const int n0   = blockIdx.x * 128;
    const int warp = t >> 5;
    const int lane = t & 31;
    const int wm   = (warp >> 1) * 32;
    const int wn   = (warp & 1) * 64;

    const int a_mloc = lane & 15;
    const int a_gsel = lane >> 4;
    const int b_nloc = (lane & 7) + ((lane & 16) >> 1);
    const int b_gsel = (lane >> 3) & 1;

    float acc[2][8][4];
#pragma unroll
    for (int mt = 0; mt < 2; mt++)
#pragma unroll
        for (int nt = 0; nt < 8; nt++)
#pragma unroll
            for (int r = 0; r < 4; r++) acc[mt][nt][r] = 0.f;

    // stage: A (hi sg0-3, lo sg4-7) 16KB at abase; B (hi sg0-3) at bbase
    auto issue = [&](int k0, int buf) {
        uint32_t abase = sbase + buf * 32768;
        uint32_t bbase = abase + 16384;
#pragma unroll
        for (int i = 0; i < 4; i++) {
            int ga = t + i * 256;
            int m = ga >> 3, sg = ga & 7;
            const __half* src = (sg < 4 ? Ah : Al)
                              + (size_t)(m0 + m) * K + k0 + (sg & 3) * 8;
            cp16(abase + m * 128 + ((sg ^ (m & 7)) << 4), src);
        }
#pragma unroll
        for (int i = 0; i < 2; i++) {
            int ga = t + i * 256;
            int n = ga >> 2, sg = ga & 3;
            const __half* src = Bh + (size_t)(n0 + n) * K + k0 + sg * 8;
            cp16(bbase + n * 128 + ((sg ^ (n & 7)) << 4), src);
        }
    };

    const int NIT = K >> 5;
    issue(0, 0);
    asm volatile("cp.async.commit_group;");
    issue(32, 1);
    asm volatile("cp.async.commit_group;");

    for (int it = 0; it < NIT; it++) {
        if (it + 2 < NIT) {
            issue((it + 2) << 5, (it + 2) % 3);
            asm volatile("cp.async.commit_group;");
            asm volatile("cp.async.wait_group 2;");
        } else if (it + 1 < NIT) {
            asm volatile("cp.async.wait_group 1;");
        } else {
            asm volatile("cp.async.wait_group 0;");
        }
        __syncthreads();

        const uint32_t abase = sbase + (it % 3) * 32768;
        const uint32_t bbase = abase + 16384;

#pragma unroll
        for (int c = 0; c < 2; c++) {
            uint32_t ah[2][4], al[2][4], bb[4][4];
#pragma unroll
            for (int mt = 0; mt < 2; mt++) {
                int m = wm + mt * 16 + a_mloc;
                int sg = 2 * c + a_gsel;
                LDSM4(ah[mt][0], ah[mt][1], ah[mt][2], ah[mt][3],
                      abase + m * 128 + ((sg ^ (m & 7)) << 4));
            }
#pragma unroll
            for (int p = 0; p < 4; p++) {
                int n = wn + p * 16 + b_nloc;
                int sg = 2 * c + b_gsel;
                LDSM4(bb[p][0], bb[p][1], bb[p][2], bb[p][3],
                      bbase + n * 128 + ((sg ^ (n & 7)) << 4));
            }
#pragma unroll
            for (int mt = 0; mt < 2; mt++)
#pragma unroll
                for (int p = 0; p < 4; p++) {
                    MMA16816(acc[mt][2 * p],     ah[mt], bb[p][0], bb[p][1]);
                    MMA16816(acc[mt][2 * p + 1], ah[mt], bb[p][2], bb[p][3]);
                }
#pragma unroll
            for (int mt = 0; mt < 2; mt++) {
                int m = wm + mt * 16 + a_mloc;
                int sg = 4 + 2 * c + a_gsel;
                LDSM4(al[mt][0], al[mt][1], al[mt][2], al[mt][3],
                      abase + m * 128 + ((sg ^ (m & 7)) << 4));
            }
#pragma unroll
            for (int mt = 0; mt < 2; mt++)
#pragma unroll
                for (int p = 0; p < 4; p++) {
                    MMA16816(acc[mt][2 * p],     al[mt], bb[p][0], bb[p][1]);
                    MMA16816(acc[mt][2 * p + 1], al[mt], bb[p][2], bb[p][3]);
                }
        }
        __syncthreads();
    }

    // ---- epilogue ----
#pragma unroll
    for (int mt = 0; mt < 2; mt++) {
        int r = m0 + wm + mt * 16 + (lane >> 2);
#pragma unroll
        for (int nt = 0; nt < 8; nt++) {
            int cc = n0 + wn + nt * 8 + (lane & 3) * 2;
            if (MODE == 0) {
                float* p0 = C + (size_t)r * N + cc;
                p0[0] = acc[mt][nt][0];
                p0[1] = acc[mt][nt][1];
                float* p1 = p0 + 8 * N;
                p1[0] = acc[mt][nt][2];
                p1[1] = acc[mt][nt][3];
            } else {
                int i = (cc & 127) >> 1;
                {
                    float cw = cosw[r * 64 + i], sw = sinw[r * 64 + i];
                    float t0 = acc[mt][nt][0], t1 = acc[mt][nt][1];
                    float r0 = (t0 * cw - t1 * sw) * scale;
                    float r1 = (t0 * sw + t1 * cw) * scale;
                    __half2 lo2, hi2 = split_pair(r0, r1, lo2);
                    *(__half2*)(Hi + (size_t)r * N + cc) = hi2;
                    *(__half2*)(Lo + (size_t)r * N + cc) = lo2;
                }
                {
                    int r8 = r + 8;
                    float cw = cosw[r8 * 64 + i], sw = sinw[r8 * 64 + i];
                    float t0 = acc[mt][nt][2], t1 = acc[mt][nt][3];
                    float r0 = (t0 * cw - t1 * sw) * scale;
                    float r1 = (t0 * sw + t1 * cw) * scale;
                    __half2 lo2, hi2 = split_pair(r0, r1, lo2);
                    *(__half2*)(Hi + (size_t)r8 * N + cc) = hi2;
                    *(__half2*)(Lo + (size_t)r8 * N + cc) = lo2;
                }
            }
        }
    }
}

// ---------------------------------------------------------------------------
// Flash attention on tensor cores, 2-stage double-buffered K/V.
// smem: Q 32KB | K[2] 2x32KB | V[2] 2x32KB = 160KB. 1 CTA/SM.
// ---------------------------------------------------------------------------
#define FQ_OFF   0
#define FK_OFF   32768
#define FV_OFF   98304
#define FST      32768     // stage stride
#define FLASH_TC_SMEM 163840

__global__ __launch_bounds__(128, 1)
void flash_tc(const __half* __restrict__ Qh, const __half* __restrict__ Ql,
              const __half* __restrict__ Kh, const __half* __restrict__ Kl,
              const __half* __restrict__ Vth, const __half* __restrict__ Vtl,
              __half* __restrict__ Oh, __half* __restrict__ Ol) {
    extern __shared__ char smc[];
    const uint32_t sb = (uint32_t)__cvta_generic_to_shared(smc);
    const int t    = threadIdx.x;
    const int lane = t & 31;
    const int warp = t >> 5;
    const int qt   = (int)gridDim.x - 1 - (int)blockIdx.x;
    const int h    = blockIdx.y;
    const int kh   = h >> 2;
    const int q0   = qt * 64;

    const int a_ml = lane & 15;
    const int a_gs = lane >> 4;
    const int b_nl = (lane & 7) + ((lane & 16) >> 1);
    const int b_gs = (lane >> 3) & 1;

    auto issue_kv = [&](int kt, int buf) {
        const int k0 = kt * 64;
        const uint32_t kb = sb + FK_OFF + buf * FST;
        const uint32_t vb = sb + FV_OFF + buf * FST;
#pragma unroll
        for (int i = 0; i < 16; i++) {
            int g = t + i * 128;
            int hf = g >> 10, gg = g & 1023;
            int r = gg >> 4, c = gg & 15;
            const __half* src = (hf ? Kl : Kh)
                              + (size_t)(k0 + r) * KV_D + kh * HDIM + c * 8;
            cp16(kb + hf * 16384 + r * 256 + ((c ^ (r & 7)) << 4), src);
        }
#pragma unroll
        for (int i = 0; i < 16; i++) {
            int g = t + i * 128;
            int hf = g >> 10, gg = g & 1023;
            int r = gg >> 3, c = gg & 7;
            const __half* src = (hf ? Vtl : Vth)
                              + (size_t)(kh * HDIM + r) * S_LEN + k0 + c * 8;
            cp16(vb + hf * 16384 + r * 128 + ((c ^ (r & 7)) << 4), src);
        }
    };

    // prologue: Q + KV(0) in one group
#pragma unroll
    for (int i = 0; i < 16; i++) {
        int g = t + i * 128;
        int hf = g >> 10, gg = g & 1023;
        int r = gg >> 4, c = gg & 15;
        const __half* src = (hf ? Ql : Qh)
                          + (size_t)(q0 + r) * D_MODEL + h * HDIM + c * 8;
        cp16(sb + FQ_OFF + hf * 16384 + r * 256 + ((c ^ (r & 7)) << 4), src);
    }
    issue_kv(0, 0);
    asm volatile("cp.async.commit_group;");

    float o[16][4];
#pragma unroll
    for (int nt = 0; nt < 16; nt++)
#pragma unroll
        for (int j = 0; j < 4; j++) o[nt][j] = 0.f;
    float m0r = -1e30f, m1r = -1e30f, l0 = 0.f, l1 = 0.f;

    for (int kt = 0; kt <= qt; kt++) {
        const int k0 = kt * 64;
        const int buf = kt & 1;

        if (kt < qt) {
            issue_kv(kt + 1, buf ^ 1);
            asm volatile("cp.async.commit_group;");
            asm volatile("cp.async.wait_group 1;");
        } else {
            asm volatile("cp.async.wait_group 0;");
        }
        __syncthreads();

        const uint32_t kb = sb + FK_OFF + buf * FST;
        const uint32_t vb = sb + FV_OFF + buf * FST;

        float sacc[8][4];
#pragma unroll
        for (int nt = 0; nt < 8; nt++)
#pragma unroll
            for (int j = 0; j < 4; j++) sacc[nt][j] = 0.f;

#pragma unroll
        for (int kc = 0; kc < 8; kc++) {
            uint32_t aqh[4], aql[4];
            {
                int r = warp * 16 + a_ml;
                int cf = 2 * kc + a_gs;
                uint32_t qa = sb + FQ_OFF + r * 256 + ((cf ^ (r & 7)) << 4);
                LDSM4(aqh[0], aqh[1], aqh[2], aqh[3], qa);
                LDSM4(aql[0], aql[1], aql[2], aql[3], qa + 16384);
            }
#pragma unroll
            for (int p = 0; p < 4; p++) {
                int n = p * 16 + b_nl;
                int cf = 2 * kc + b_gs;
                uint32_t ka = kb + n * 256 + ((cf ^ (n & 7)) << 4);
                uint32_t bh[4], bl[4];
                LDSM4(bh[0], bh[1], bh[2], bh[3], ka);
                LDSM4(bl[0], bl[1], bl[2], bl[3], ka + 16384);
                MMA16816(sacc[2 * p],     aqh, bh[0], bh[1]);
                MMA16816(sacc[2 * p + 1], aqh, bh[2], bh[3]);
                MMA16816(sacc[2 * p],     aqh, bl[0], bl[1]);
                MMA16816(sacc[2 * p + 1], aqh, bl[2], bl[3]);
                MMA16816(sacc[2 * p],     aql, bh[0], bh[1]);
                MMA16816(sacc[2 * p + 1], aql, bh[2], bh[3]);
            }
        }

        if (kt == qt) {
            int rg0 = q0 + warp * 16 + (lane >> 2);
#pragma unroll
            for (int nt = 0; nt < 8; nt++) {
                int cg = k0 + nt * 8 + (lane & 3) * 2;
                if (cg     > rg0)     sacc[nt][0] += -1e9f;
                if (cg + 1 > rg0)     sacc[nt][1] += -1e9f;
                if (cg     > rg0 + 8) sacc[nt][2] += -1e9f;
                if (cg + 1 > rg0 + 8) sacc[nt][3] += -1e9f;
            }
        }

        float rmax0 = -1e30f, rmax1 = -1e30f;
#pragma unroll
        for (int nt = 0; nt < 8; nt++) {
            rmax0 = fmaxf(rmax0, fmaxf(sacc[nt][0], sacc[nt][1]));
            rmax1 = fmaxf(rmax1, fmaxf(sacc[nt][2], sacc[nt][3]));
        }
#pragma unroll
        for (int off = 1; off < 4; off <<= 1) {
            rmax0 = fmaxf(rmax0, __shfl_xor_sync(0xffffffffu, rmax0, off));
            rmax1 = fmaxf(rmax1, __shfl_xor_sync(0xffffffffu, rmax1, off));
        }
        float mn0 = fmaxf(m0r, rmax0), mn1 = fmaxf(m1r, rmax1);
        float al0 = __expf(m0r - mn0), al1 = __expf(m1r - mn1);
        m0r = mn0; m1r = mn1;

        float rs0 = 0.f, rs1 = 0.f;
#pragma unroll
        for (int nt = 0; nt < 8; nt++) {
            sacc[nt][0] = __expf(sacc[nt][0] - mn0);
            sacc[nt][1] = __expf(sacc[nt][1] - mn0);
            sacc[nt][2] = __expf(sacc[nt][2] - mn1);
            sacc[nt][3] = __expf(sacc[nt][3] - mn1);
            rs0 += sacc[nt][0] + sacc[nt][1];
            rs1 += sacc[nt][2] + sacc[nt][3];
        }
#pragma unroll
        for (int off = 1; off < 4; off <<= 1) {
            rs0 += __shfl_xor_sync(0xffffffffu, rs0, off);
            rs1 += __shfl_xor_sync(0xffffffffu, rs1, off);
        }
        l0 = l0 * al0 + rs0;
        l1 = l1 * al1 + rs1;
#pragma unroll
        for (int nt = 0; nt < 16; nt++) {
            o[nt][0] *= al0; o[nt][1] *= al0;
            o[nt][2] *= al1; o[nt][3] *= al1;
        }

#pragma unroll
        for (int kc = 0; kc < 4; kc++) {
            uint32_t ph[4], pl[4];
            {
                __half2 l2;
                __half2 h2 = split_pair(sacc[2*kc][0], sacc[2*kc][1], l2);
                ph[0] = *(uint32_t*)&h2; pl[0] = *(uint32_t*)&l2;
                h2 = split_pair(sacc[2*kc][2], sacc[2*kc][3], l2);
                ph[1] = *(uint32_t*)&h2; pl[1] = *(uint32_t*)&l2;
                h2 = split_pair(sacc[2*kc+1][0], sacc[2*kc+1][1], l2);
                ph[2] = *(uint32_t*)&h2; pl[2] = *(uint32_t*)&l2;
                h2 = split_pair(sacc[2*kc+1][2], sacc[2*kc+1][3], l2);
                ph[3] = *(uint32_t*)&h2; pl[3] = *(uint32_t*)&l2;
            }
#pragma unroll
            for (int p = 0; p < 8; p++) {
                int n = p * 16 + b_nl;
                int cf = 2 * kc + b_gs;
                uint32_t va = vb + n * 128 + ((cf ^ (n & 7)) << 4);
                uint32_t bh[4], bl[4];
                LDSM4(bh[0], bh[1], bh[2], bh[3], va);
                LDSM4(bl[0], bl[1], bl[2], bl[3], va + 16384);
                MMA16816(o[2 * p],     ph, bh[0], bh[1]);
                MMA16816(o[2 * p + 1], ph, bh[2], bh[3]);
                MMA16816(o[2 * p],     ph, bl[0], bl[1]);
                MMA16816(o[2 * p + 1], ph, bl[2], bl[3]);
                MMA16816(o[2 * p],     pl, bh[0], bh[1]);
                MMA16816(o[2 * p + 1], pl, bh[2], bh[3]);
            }
        }
        __syncthreads();   // all warps done reading buf before it's re-filled
    }

    float inv0 = 1.f / l0, inv1 = 1.f / l1;
    int rg0 = q0 + warp * 16 + (lane >> 2);
#pragma unroll
    for (int nt = 0; nt < 16; nt++) {
        int col = h * HDIM + nt * 8 + (lane & 3) * 2;
        {
            __half2 lo2, hi2 = split_pair(o[nt][0] * inv0, o[nt][1] * inv0, lo2);
            *(__half2*)(Oh + (size_t)rg0 * D_MODEL + col) = hi2;
            *(__half2*)(Ol + (size_t)rg0 * D_MODEL + col) = lo2;
        }
        {
            __half2 lo2, hi2 = split_pair(o[nt][2] * inv1, o[nt][3] * inv1, lo2);
            *(__half2*)(Oh + (size_t)(rg0 + 8) * D_MODEL + col) = hi2;
            *(__half2*)(Ol + (size_t)(rg0 + 8) * D_MODEL + col) = lo2;
        }
    }
}

// ---------------------------------------------------------------------------
extern "C" void kernel_launch(void* const* d_in, const int* in_sizes, int n_in,
                              void* d_out, int out_size) {
    const float* x  = (const float*)d_in[0];
    const float* fc = (const float*)d_in[1];
    const float* fs = (const float*)d_in[2];
    const float* wq = (const float*)d_in[4];
    const float* wk = (const float*)d_in[5];
    const float* wv = (const float*)d_in[6];
    const float* wo = (const float*)d_in[7];
    float* out = (float*)d_out;

    float* vp;
    cudaGetSymbolAddress((void**)&vp, g_V);

    __half *xh, *xl, *wqh, *wkh, *wvh, *woh, *ah, *al;
    __half *qfh, *qfl, *kfh, *kfl, *vth, *vtl;
    cudaGetSymbolAddress((void**)&xh,  g_xh);  cudaGetSymbolAddress((void**)&xl,  g_xl);
    cudaGetSymbolAddress((void**)&wqh, g_wqh);
    cudaGetSymbolAddress((void**)&wkh, g_wkh);
    cudaGetSymbolAddress((void**)&wvh, g_wvh);
    cudaGetSymbolAddress((void**)&woh, g_woh);
    cudaGetSymbolAddress((void**)&ah,  g_ah);  cudaGetSymbolAddress((void**)&al,  g_al);
    cudaGetSymbolAddress((void**)&qfh, g_Qfh); cudaGetSymbolAddress((void**)&qfl, g_Qfl);
    cudaGetSymbolAddress((void**)&kfh, g_Kfh); cudaGetSymbolAddress((void**)&kfl, g_Kfl);
    cudaGetSymbolAddress((void**)&vth, g_Vth); cudaGetSymbolAddress((void**)&vtl, g_Vtl);

    cudaFuncSetAttribute((const void*)hgemm_split<0>,
                         cudaFuncAttributeMaxDynamicSharedMemorySize, HGEMM_SMEM);
    cudaFuncSetAttribute((const void*)hgemm_split<1>,
                         cudaFuncAttributeMaxDynamicSharedMemorySize, HGEMM_SMEM);
    cudaFuncSetAttribute((const void*)flash_tc,
                         cudaFuncAttributeMaxDynamicSharedMemorySize, FLASH_TC_SMEM);

    const int NX  = S_LEN * D_MODEL;
    const int NW  = D_MODEL * D_MODEL;
    const int NKW = KV_D * D_MODEL;

    split_h<<<(NX + 255) / 256, 256>>>(x, xh, xl, NX);
    cvt_h<<<(NW  + 255) / 256, 256>>>(wq, wqh, NW);
    cvt_h<<<(NKW + 255) / 256, 256>>>(wk, wkh, NKW);
    cvt_h<<<(NKW + 255) / 256, 256>>>(wv, wvh, NKW);
    cvt_h<<<(NW  + 255) / 256, 256>>>(wo, woh, NW);

    // Q/K projections with fused rope+scale+split epilogue
    hgemm_split<1><<<dim3(32, 16), 256, HGEMM_SMEM>>>(
        xh, xl, wqh, nullptr, qfh, qfl, fc, fs, ATT_SCALE,
        S_LEN, NH * HDIM, D_MODEL);
    hgemm_split<1><<<dim3(8, 16), 256, HGEMM_SMEM>>>(
        xh, xl, wkh, nullptr, kfh, kfl, fc, fs, 1.f,
        S_LEN, KV_D, D_MODEL);
    // V projection + transpose/split
    hgemm_split<0><<<dim3(8, 16), 256, HGEMM_SMEM>>>(
        xh, xl, wvh, vp, nullptr, nullptr, nullptr, nullptr, 1.f,
        S_LEN, KV_D, D_MODEL);
    transpose_split_v<<<dim3(S_LEN / 32, KV_D / 32), dim3(32, 8)>>>(vp, vth, vtl);

    // Flash attention (double-buffered K/V), split-fp16 out
    flash_tc<<<dim3(32, 32), 128, FLASH_TC_SMEM>>>(qfh, qfl, kfh, kfl, vth, vtl,
                                                   ah, al);

    // Output projection (2-term)
    hgemm_split<0><<<dim3(32, 16), 256, HGEMM_SMEM>>>(
        ah, al, woh, out, nullptr, nullptr, nullptr, nullptr, 1.f,
        S_LEN, D_MODEL, D_MODEL);
}

// round 13
// speedup vs baseline: 1.2582x; 1.2582x over previous
#include <cuda_runtime.h>
#include <cuda_fp16.h>
#include <math.h>
#include <stdint.h>

#define S_LEN   2048
#define D_MODEL 4096
#define NH      32
#define NKV     8
#define HDIM    128
#define KV_D    (NKV * HDIM)           // 1024
#define ATT_SCALE 0.08838834764831843f // 128^-0.5

// ---------------- static scratch (allocation forbidden) --------------------
__device__ float g_V[S_LEN * KV_D];

__device__ __half g_xh[S_LEN * D_MODEL];
__device__ __half g_wqh[D_MODEL * D_MODEL];
__device__ __half g_wkh[KV_D * D_MODEL];
__device__ __half g_wvh[KV_D * D_MODEL];
__device__ __half g_woh[D_MODEL * D_MODEL];
__device__ __half g_ah[S_LEN * D_MODEL], g_al[S_LEN * D_MODEL];

__device__ __half g_Qfh[S_LEN * D_MODEL], g_Qfl[S_LEN * D_MODEL];  // rope'd, scaled
__device__ __half g_Kfh[S_LEN * KV_D],    g_Kfl[S_LEN * KV_D];     // rope'd
__device__ __half g_Vth[KV_D * S_LEN],    g_Vtl[KV_D * S_LEN];     // [kvh*128+d][s]

// ---------------------------------------------------------------------------
__device__ __forceinline__ void cp16(uint32_t dst, const void* src) {
    asm volatile("cp.async.cg.shared.global [%0], [%1], 16;\n" :: "r"(dst), "l"(src));
}
#define LDSM4(R0, R1, R2, R3, ADDR)                                          \
    asm volatile("ldmatrix.sync.aligned.m8n8.x4.shared.b16 {%0,%1,%2,%3},[%4];" \
                 : "=r"(R0), "=r"(R1), "=r"(R2), "=r"(R3) : "r"(ADDR))
#define MMA16816(C, A, B0, B1)                                               \
    asm volatile("mma.sync.aligned.m16n8k16.row.col.f32.f16.f16.f32 "        \
                 "{%0,%1,%2,%3},{%4,%5,%6,%7},{%8,%9},{%0,%1,%2,%3};"        \
                 : "+f"((C)[0]), "+f"((C)[1]), "+f"((C)[2]), "+f"((C)[3])    \
                 : "r"((A)[0]), "r"((A)[1]), "r"((A)[2]), "r"((A)[3]),       \
                   "r"(B0), "r"(B1))

__device__ __forceinline__ __half2 split_pair(float a, float b, __half2& lo) {
    __half ah = __float2half_rn(a), bh = __float2half_rn(b);
    lo = __halves2half2(__float2half_rn(a - __half2float(ah)),
                        __float2half_rn(b - __half2float(bh)));
    return __halves2half2(ah, bh);
}

// ---------------------------------------------------------------------------
__global__ void cvt_h(const float* __restrict__ in, __half* __restrict__ hi, int n) {
    int i = blockIdx.x * blockDim.x + threadIdx.x;
    if (i >= n) return;
    hi[i] = __float2half_rn(in[i]);
}

// ---------------------------------------------------------------------------
__global__ void transpose_split_v(const float* __restrict__ V,
                                  __half* __restrict__ Vth,
                                  __half* __restrict__ Vtl) {
    __shared__ float tile[32][33];
    const int s0 = blockIdx.x * 32, d0 = blockIdx.y * 32;
    const int tx = threadIdx.x, ty = threadIdx.y;
#pragma unroll
    for (int i = 0; i < 4; i++)
        tile[ty + 8 * i][tx] = V[(size_t)(s0 + ty + 8 * i) * KV_D + d0 + tx];
    __syncthreads();
#pragma unroll
    for (int i = 0; i < 4; i++) {
        int d = d0 + ty + 8 * i, s = s0 + tx;
        float v = tile[tx][ty + 8 * i];
        __half h = __float2half_rn(v);
        Vth[(size_t)d * S_LEN + s] = h;
        Vtl[(size_t)d * S_LEN + s] = __float2half_rn(v - __half2float(h));
    }
}

// ---------------------------------------------------------------------------
// HGEMM: C = A @ Bh^T (TERMS=1: A=Ah; TERMS=2: A=Ah+Al), fp32 accum.
// MODE 0: fp32 C out. MODE 1: rope+scale+split-fp16 out.
// 128x128 tile, k32, 3-stage cp.async ring, 256 threads, 2 CTAs/SM.
// ---------------------------------------------------------------------------
#define HGEMM_SMEM (3 * 32768)

template<int MODE, int TERMS>
__global__ __launch_bounds__(256, 2)
void hgemm_split(const __half* __restrict__ Ah, const __half* __restrict__ Al,
                 const __half* __restrict__ Bh,
                 float* __restrict__ C,
                 __half* __restrict__ Hi, __half* __restrict__ Lo,
                 const float* __restrict__ cosw, const float* __restrict__ sinw,
                 float scale, int M, int N, int K) {
    extern __shared__ __half smh[];
    const uint32_t sbase = (uint32_t)__cvta_generic_to_shared(smh);

    const int t    = threadIdx.x;
    const int m0   = blockIdx.y * 128;
    const int n0   = blockIdx.x * 128;
    const int warp = t >> 5;
    const int lane = t & 31;
    const int wm   = (warp >> 1) * 32;
    const int wn   = (warp & 1) * 64;

    const int a_mloc = lane & 15;
    const int a_gsel = lane >> 4;
    const int b_nloc = (lane & 7) + ((lane & 16) >> 1);
    const int b_gsel = (lane >> 3) & 1;

    float acc[2][8][4];
#pragma unroll
    for (int mt = 0; mt < 2; mt++)
#pragma unroll
        for (int nt = 0; nt < 8; nt++)
#pragma unroll
            for (int r = 0; r < 4; r++) acc[mt][nt][r] = 0.f;

    // stage layout: A 16KB at abase (sg 0-3 hi, sg 4-7 lo if TERMS=2);
    //               B 16KB at bbase (sg 0-3 hi). 128B row stride throughout.
    auto issue = [&](int k0, int buf) {
        uint32_t abase = sbase + buf * 32768;
        uint32_t bbase = abase + 16384;
        const int AIT = (TERMS == 2) ? 4 : 2;
#pragma unroll
        for (int i = 0; i < 4; i++) {
            if (i >= AIT) break;
            int ga = t + i * 256;
            int m, sg;
            if (TERMS == 2) { m = ga >> 3; sg = ga & 7; }
            else            { m = ga >> 2; sg = ga & 3; }
            const __half* src = ((TERMS == 2 && sg >= 4) ? Al : Ah)
                              + (size_t)(m0 + m) * K + k0 + (sg & 3) * 8;
            cp16(abase + m * 128 + ((sg ^ (m & 7)) << 4), src);
        }
#pragma unroll
        for (int i = 0; i < 2; i++) {
            int ga = t + i * 256;
            int n = ga >> 2, sg = ga & 3;
            const __half* src = Bh + (size_t)(n0 + n) * K + k0 + sg * 8;
            cp16(bbase + n * 128 + ((sg ^ (n & 7)) << 4), src);
        }
    };

    const int NIT = K >> 5;
    issue(0, 0);
    asm volatile("cp.async.commit_group;");
    issue(32, 1);
    asm volatile("cp.async.commit_group;");

    for (int it = 0; it < NIT; it++) {
        if (it + 2 < NIT) {
            issue((it + 2) << 5, (it + 2) % 3);
            asm volatile("cp.async.commit_group;");
            asm volatile("cp.async.wait_group 2;");
        } else if (it + 1 < NIT) {
            asm volatile("cp.async.wait_group 1;");
        } else {
            asm volatile("cp.async.wait_group 0;");
        }
        __syncthreads();

        const uint32_t abase = sbase + (it % 3) * 32768;
        const uint32_t bbase = abase + 16384;

#pragma unroll
        for (int c = 0; c < 2; c++) {
            uint32_t ah[2][4], bb[4][4];
#pragma unroll
            for (int mt = 0; mt < 2; mt++) {
                int m = wm + mt * 16 + a_mloc;
                int sg = 2 * c + a_gsel;
                LDSM4(ah[mt][0], ah[mt][1], ah[mt][2], ah[mt][3],
                      abase + m * 128 + ((sg ^ (m & 7)) << 4));
            }
#pragma unroll
            for (int p = 0; p < 4; p++) {
                int n = wn + p * 16 + b_nloc;
                int sg = 2 * c + b_gsel;
                LDSM4(bb[p][0], bb[p][1], bb[p][2], bb[p][3],
                      bbase + n * 128 + ((sg ^ (n & 7)) << 4));
            }
#pragma unroll
            for (int mt = 0; mt < 2; mt++)
#pragma unroll
                for (int p = 0; p < 4; p++) {
                    MMA16816(acc[mt][2 * p],     ah[mt], bb[p][0], bb[p][1]);
                    MMA16816(acc[mt][2 * p + 1], ah[mt], bb[p][2], bb[p][3]);
                }
            if (TERMS == 2) {
                uint32_t al[2][4];
#pragma unroll
                for (int mt = 0; mt < 2; mt++) {
                    int m = wm + mt * 16 + a_mloc;
                    int sg = 4 + 2 * c + a_gsel;
                    LDSM4(al[mt][0], al[mt][1], al[mt][2], al[mt][3],
                          abase + m * 128 + ((sg ^ (m & 7)) << 4));
                }
#pragma unroll
                for (int mt = 0; mt < 2; mt++)
#pragma unroll
                    for (int p = 0; p < 4; p++) {
                        MMA16816(acc[mt][2 * p],     al[mt], bb[p][0], bb[p][1]);
                        MMA16816(acc[mt][2 * p + 1], al[mt], bb[p][2], bb[p][3]);
                    }
            }
        }
        __syncthreads();
    }

    // ---- epilogue ----
#pragma unroll
    for (int mt = 0; mt < 2; mt++) {
        int r = m0 + wm + mt * 16 + (lane >> 2);
#pragma unroll
        for (int nt = 0; nt < 8; nt++) {
            int cc = n0 + wn + nt * 8 + (lane & 3) * 2;
            if (MODE == 0) {
                float* p0 = C + (size_t)r * N + cc;
                p0[0] = acc[mt][nt][0];
                p0[1] = acc[mt][nt][1];
                float* p1 = p0 + 8 * N;
                p1[0] = acc[mt][nt][2];
                p1[1] = acc[mt][nt][3];
            } else {
                int i = (cc & 127) >> 1;
                {
                    float cw = cosw[r * 64 + i], sw = sinw[r * 64 + i];
                    float t0 = acc[mt][nt][0], t1 = acc[mt][nt][1];
                    float r0 = (t0 * cw - t1 * sw) * scale;
                    float r1 = (t0 * sw + t1 * cw) * scale;
                    __half2 lo2, hi2 = split_pair(r0, r1, lo2);
                    *(__half2*)(Hi + (size_t)r * N + cc) = hi2;
                    *(__half2*)(Lo + (size_t)r * N + cc) = lo2;
                }
                {
                    int r8 = r + 8;
                    float cw = cosw[r8 * 64 + i], sw = sinw[r8 * 64 + i];
                    float t0 = acc[mt][nt][2], t1 = acc[mt][nt][3];
                    float r0 = (t0 * cw - t1 * sw) * scale;
                    float r1 = (t0 * sw + t1 * cw) * scale;
                    __half2 lo2, hi2 = split_pair(r0, r1, lo2);
                    *(__half2*)(Hi + (size_t)r8 * N + cc) = hi2;
                    *(__half2*)(Lo + (size_t)r8 * N + cc) = lo2;
                }
            }
        }
    }
}

// ---------------------------------------------------------------------------
// Flash attention on tensor cores (split-fp16, 3-term), split-fp16 output.
// Single-buffered (R9 layout — 96KB smem, 2 CTAs/SM residency possible).
// ---------------------------------------------------------------------------
#define FQ_OFF  0
#define FK_OFF  32768
#define FV_OFF  65536
#define FLASH_TC_SMEM 98304

__global__ __launch_bounds__(128, 1)
void flash_tc(const __half* __restrict__ Qh, const __half* __restrict__ Ql,
              const __half* __restrict__ Kh, const __half* __restrict__ Kl,
              const __half* __restrict__ Vth, const __half* __restrict__ Vtl,
              __half* __restrict__ Oh, __half* __restrict__ Ol) {
    extern __shared__ char smc[];
    const uint32_t sb = (uint32_t)__cvta_generic_to_shared(smc);
    const int t    = threadIdx.x;
    const int lane = t & 31;
    const int warp = t >> 5;
    const int qt   = (int)gridDim.x - 1 - (int)blockIdx.x;
    const int h    = blockIdx.y;
    const int kh   = h >> 2;
    const int q0   = qt * 64;

    const int a_ml = lane & 15;
    const int a_gs = lane >> 4;
    const int b_nl = (lane & 7) + ((lane & 16) >> 1);
    const int b_gs = (lane >> 3) & 1;

#pragma unroll
    for (int i = 0; i < 16; i++) {
        int g = t + i * 128;
        int hf = g >> 10, gg = g & 1023;
        int r = gg >> 4, c = gg & 15;
        const __half* src = (hf ? Ql : Qh)
                          + (size_t)(q0 + r) * D_MODEL + h * HDIM + c * 8;
        cp16(sb + FQ_OFF + hf * 16384 + r * 256 + ((c ^ (r & 7)) << 4), src);
    }
    asm volatile("cp.async.commit_group;");

    float o[16][4];
#pragma unroll
    for (int nt = 0; nt < 16; nt++)
#pragma unroll
        for (int j = 0; j < 4; j++) o[nt][j] = 0.f;
    float m0r = -1e30f, m1r = -1e30f, l0 = 0.f, l1 = 0.f;

    for (int kt = 0; kt <= qt; kt++) {
        const int k0 = kt * 64;
        __syncthreads();
#pragma unroll
        for (int i = 0; i < 16; i++) {
            int g = t + i * 128;
            int hf = g >> 10, gg = g & 1023;
            int r = gg >> 4, c = gg & 15;
            const __half* src = (hf ? Kl : Kh)
                              + (size_t)(k0 + r) * KV_D + kh * HDIM + c * 8;
            cp16(sb + FK_OFF + hf * 16384 + r * 256 + ((c ^ (r & 7)) << 4), src);
        }
#pragma unroll
        for (int i = 0; i < 16; i++) {
            int g = t + i * 128;
            int hf = g >> 10, gg = g & 1023;
            int r = gg >> 3, c = gg & 7;
            const __half* src = (hf ? Vtl : Vth)
                              + (size_t)(kh * HDIM + r) * S_LEN + k0 + c * 8;
            cp16(sb + FV_OFF + hf * 16384 + r * 128 + ((c ^ (r & 7)) << 4), src);
        }
        asm volatile("cp.async.commit_group;");
        asm volatile("cp.async.wait_group 0;");
        __syncthreads();

        float sacc[8][4];
#pragma unroll
        for (int nt = 0; nt < 8; nt++)
#pragma unroll
            for (int j = 0; j < 4; j++) sacc[nt][j] = 0.f;

#pragma unroll
        for (int kc = 0; kc < 8; kc++) {
            uint32_t aqh[4], aql[4];
            {
                int r = warp * 16 + a_ml;
                int cf = 2 * kc + a_gs;
                uint32_t qa = sb + FQ_OFF + r * 256 + ((cf ^ (r & 7)) << 4);
                LDSM4(aqh[0], aqh[1], aqh[2], aqh[3], qa);
                LDSM4(aql[0], aql[1], aql[2], aql[3], qa + 16384);
            }
#pragma unroll
            for (int p = 0; p < 4; p++) {
                int n = p * 16 + b_nl;
                int cf = 2 * kc + b_gs;
                uint32_t ka = sb + FK_OFF + n * 256 + ((cf ^ (n & 7)) << 4);
                uint32_t bh[4], bl[4];
                LDSM4(bh[0], bh[1], bh[2], bh[3], ka);
                LDSM4(bl[0], bl[1], bl[2], bl[3], ka + 16384);
                MMA16816(sacc[2 * p],     aqh, bh[0], bh[1]);
                MMA16816(sacc[2 * p + 1], aqh, bh[2], bh[3]);
                MMA16816(sacc[2 * p],     aqh, bl[0], bl[1]);
                MMA16816(sacc[2 * p + 1], aqh, bl[2], bl[3]);
                MMA16816(sacc[2 * p],     aql, bh[0], bh[1]);
                MMA16816(sacc[2 * p + 1], aql, bh[2], bh[3]);
            }
        }

        if (kt == qt) {
            int rg0 = q0 + warp * 16 + (lane >> 2);
#pragma unroll
            for (int nt = 0; nt < 8; nt++) {
                int cg = k0 + nt * 8 + (lane & 3) * 2;
                if (cg     > rg0)     sacc[nt][0] += -1e9f;
                if (cg + 1 > rg0)     sacc[nt][1] += -1e9f;
                if (cg     > rg0 + 8) sacc[nt][2] += -1e9f;
                if (cg + 1 > rg0 + 8) sacc[nt][3] += -1e9f;
            }
        }

        float rmax0 = -1e30f, rmax1 = -1e30f;
#pragma unroll
        for (int nt = 0; nt < 8; nt++) {
            rmax0 = fmaxf(rmax0, fmaxf(sacc[nt][0], sacc[nt][1]));
            rmax1 = fmaxf(rmax1, fmaxf(sacc[nt][2], sacc[nt][3]));
        }
#pragma unroll
        for (int off = 1; off < 4; off <<= 1) {
            rmax0 = fmaxf(rmax0, __shfl_xor_sync(0xffffffffu, rmax0, off));
            rmax1 = fmaxf(rmax1, __shfl_xor_sync(0xffffffffu, rmax1, off));
        }
        float mn0 = fmaxf(m0r, rmax0), mn1 = fmaxf(m1r, rmax1);
        float al0 = __expf(m0r - mn0), al1 = __expf(m1r - mn1);
        m0r = mn0; m1r = mn1;

        float rs0 = 0.f, rs1 = 0.f;
#pragma unroll
        for (int nt = 0; nt < 8; nt++) {
            sacc[nt][0] = __expf(sacc[nt][0] - mn0);
            sacc[nt][1] = __expf(sacc[nt][1] - mn0);
            sacc[nt][2] = __expf(sacc[nt][2] - mn1);
            sacc[nt][3] = __expf(sacc[nt][3] - mn1);
            rs0 += sacc[nt][0] + sacc[nt][1];
            rs1 += sacc[nt][2] + sacc[nt][3];
        }
#pragma unroll
        for (int off = 1; off < 4; off <<= 1) {
            rs0 += __shfl_xor_sync(0xffffffffu, rs0, off);
            rs1 += __shfl_xor_sync(0xffffffffu, rs1, off);
        }
        l0 = l0 * al0 + rs0;
        l1 = l1 * al1 + rs1;
#pragma unroll
        for (int nt = 0; nt < 16; nt++) {
            o[nt][0] *= al0; o[nt][1] *= al0;
            o[nt][2] *= al1; o[nt][3] *= al1;
        }

#pragma unroll
        for (int kc = 0; kc < 4; kc++) {
            uint32_t ph[4], pl[4];
            {
                __half2 l2;
                __half2 h2 = split_pair(sacc[2*kc][0], sacc[2*kc][1], l2);
                ph[0] = *(uint32_t*)&h2; pl[0] = *(uint32_t*)&l2;
                h2 = split_pair(sacc[2*kc][2], sacc[2*kc][3], l2);
                ph[1] = *(uint32_t*)&h2; pl[1] = *(uint32_t*)&l2;
                h2 = split_pair(sacc[2*kc+1][0], sacc[2*kc+1][1], l2);
                ph[2] = *(uint32_t*)&h2; pl[2] = *(uint32_t*)&l2;
                h2 = split_pair(sacc[2*kc+1][2], sacc[2*kc+1][3], l2);
                ph[3] = *(uint32_t*)&h2; pl[3] = *(uint32_t*)&l2;
            }
#pragma unroll
            for (int p = 0; p < 8; p++) {
                int n = p * 16 + b_nl;
                int cf = 2 * kc + b_gs;
                uint32_t va = sb + FV_OFF + n * 128 + ((cf ^ (n & 7)) << 4);
                uint32_t bh[4], bl[4];
                LDSM4(bh[0], bh[1], bh[2], bh[3], va);
                LDSM4(bl[0], bl[1], bl[2], bl[3], va + 16384);
                MMA16816(o[2 * p],     ph, bh[0], bh[1]);
                MMA16816(o[2 * p + 1], ph, bh[2], bh[3]);
                MMA16816(o[2 * p],     ph, bl[0], bl[1]);
                MMA16816(o[2 * p + 1], ph, bl[2], bl[3]);
                MMA16816(o[2 * p],     pl, bh[0], bh[1]);
                MMA16816(o[2 * p + 1], pl, bh[2], bh[3]);
            }
        }
    }

    float inv0 = 1.f / l0, inv1 = 1.f / l1;
    int rg0 = q0 + warp * 16 + (lane >> 2);
#pragma unroll
    for (int nt = 0; nt < 16; nt++) {
        int col = h * HDIM + nt * 8 + (lane & 3) * 2;
        {
            __half2 lo2, hi2 = split_pair(o[nt][0] * inv0, o[nt][1] * inv0, lo2);
            *(__half2*)(Oh + (size_t)rg0 * D_MODEL + col) = hi2;
            *(__half2*)(Ol + (size_t)rg0 * D_MODEL + col) = lo2;
        }
        {
            __half2 lo2, hi2 = split_pair(o[nt][2] * inv1, o[nt][3] * inv1, lo2);
            *(__half2*)(Oh + (size_t)(rg0 + 8) * D_MODEL + col) = hi2;
            *(__half2*)(Ol + (size_t)(rg0 + 8) * D_MODEL + col) = lo2;
        }
    }
}

// ---------------------------------------------------------------------------
extern "C" void kernel_launch(void* const* d_in, const int* in_sizes, int n_in,
                              void* d_out, int out_size) {
    const float* x  = (const float*)d_in[0];
    const float* fc = (const float*)d_in[1];
    const float* fs = (const float*)d_in[2];
    const float* wq = (const float*)d_in[4];
    const float* wk = (const float*)d_in[5];
    const float* wv = (const float*)d_in[6];
    const float* wo = (const float*)d_in[7];
    float* out = (float*)d_out;

    float* vp;
    cudaGetSymbolAddress((void**)&vp, g_V);

    __half *xh, *wqh, *wkh, *wvh, *woh, *ah, *al;
    __half *qfh, *qfl, *kfh, *kfl, *vth, *vtl;
    cudaGetSymbolAddress((void**)&xh,  g_xh);
    cudaGetSymbolAddress((void**)&wqh, g_wqh);
    cudaGetSymbolAddress((void**)&wkh, g_wkh);
    cudaGetSymbolAddress((void**)&wvh, g_wvh);
    cudaGetSymbolAddress((void**)&woh, g_woh);
    cudaGetSymbolAddress((void**)&ah,  g_ah);  cudaGetSymbolAddress((void**)&al,  g_al);
    cudaGetSymbolAddress((void**)&qfh, g_Qfh); cudaGetSymbolAddress((void**)&qfl, g_Qfl);
    cudaGetSymbolAddress((void**)&kfh, g_Kfh); cudaGetSymbolAddress((void**)&kfl, g_Kfl);
    cudaGetSymbolAddress((void**)&vth, g_Vth); cudaGetSymbolAddress((void**)&vtl, g_Vtl);

    cudaFuncSetAttribute((const void*)hgemm_split<0, 1>,
                         cudaFuncAttributeMaxDynamicSharedMemorySize, HGEMM_SMEM);
    cudaFuncSetAttribute((const void*)hgemm_split<1, 1>,
                         cudaFuncAttributeMaxDynamicSharedMemorySize, HGEMM_SMEM);
    cudaFuncSetAttribute((const void*)hgemm_split<0, 2>,
                         cudaFuncAttributeMaxDynamicSharedMemorySize, HGEMM_SMEM);
    cudaFuncSetAttribute((const void*)flash_tc,
                         cudaFuncAttributeMaxDynamicSharedMemorySize, FLASH_TC_SMEM);

    const int NX  = S_LEN * D_MODEL;
    const int NW  = D_MODEL * D_MODEL;
    const int NKW = KV_D * D_MODEL;

    cvt_h<<<(NX  + 255) / 256, 256>>>(x,  xh,  NX);
    cvt_h<<<(NW  + 255) / 256, 256>>>(wq, wqh, NW);
    cvt_h<<<(NKW + 255) / 256, 256>>>(wk, wkh, NKW);
    cvt_h<<<(NKW + 255) / 256, 256>>>(wv, wvh, NKW);
    cvt_h<<<(NW  + 255) / 256, 256>>>(wo, woh, NW);

    // Q/K projections (1-term), fused rope+scale+split epilogue
    hgemm_split<1, 1><<<dim3(32, 16), 256, HGEMM_SMEM>>>(
        xh, nullptr, wqh, nullptr, qfh, qfl, fc, fs, ATT_SCALE,
        S_LEN, NH * HDIM, D_MODEL);
    hgemm_split<1, 1><<<dim3(8, 16), 256, HGEMM_SMEM>>>(
        xh, nullptr, wkh, nullptr, kfh, kfl, fc, fs, 1.f,
        S_LEN, KV_D, D_MODEL);
    // V projection (1-term) + transpose/split
    hgemm_split<0, 1><<<dim3(8, 16), 256, HGEMM_SMEM>>>(
        xh, nullptr, wvh, vp, nullptr, nullptr, nullptr, nullptr, 1.f,
        S_LEN, KV_D, D_MODEL);
    transpose_split_v<<<dim3(S_LEN / 32, KV_D / 32), dim3(32, 8)>>>(vp, vth, vtl);

    // Flash attention (tensor cores, 3-term), split-fp16 out
    flash_tc<<<dim3(32, 32), 128, FLASH_TC_SMEM>>>(qfh, qfl, kfh, kfl, vth, vtl,
                                                   ah, al);

    // Output projection (2-term A = flash output hi+lo)
    hgemm_split<0, 2><<<dim3(32, 16), 256, HGEMM_SMEM>>>(
        ah, al, woh, out, nullptr, nullptr, nullptr, nullptr, 1.f,
        S_LEN, D_MODEL, D_MODEL);
}

// round 14
// speedup vs baseline: 1.4909x; 1.1850x over previous
#include <cuda_runtime.h>
#include <cuda_fp16.h>
#include <math.h>
#include <stdint.h>

#define S_LEN   2048
#define D_MODEL 4096
#define NH      32
#define NKV     8
#define HDIM    128
#define KV_D    (NKV * HDIM)           // 1024
#define ATT_SCALE 0.08838834764831843f // 128^-0.5

// ---------------- static scratch (allocation forbidden) --------------------
__device__ float g_V[S_LEN * KV_D];

__device__ __half g_xh[S_LEN * D_MODEL];
__device__ __half g_wqh[D_MODEL * D_MODEL];
__device__ __half g_wkh[KV_D * D_MODEL];
__device__ __half g_wvh[KV_D * D_MODEL];
__device__ __half g_woh[D_MODEL * D_MODEL];
__device__ __half g_ah[S_LEN * D_MODEL];

__device__ __half g_Qfh[S_LEN * D_MODEL], g_Qfl[S_LEN * D_MODEL];  // rope'd, scaled
__device__ __half g_Kfh[S_LEN * KV_D],    g_Kfl[S_LEN * KV_D];     // rope'd
__device__ __half g_Vth[KV_D * S_LEN],    g_Vtl[KV_D * S_LEN];     // [kvh*128+d][s]

// ---------------------------------------------------------------------------
__device__ __forceinline__ void cp16(uint32_t dst, const void* src) {
    asm volatile("cp.async.cg.shared.global [%0], [%1], 16;\n" :: "r"(dst), "l"(src));
}
#define LDSM4(R0, R1, R2, R3, ADDR)                                          \
    asm volatile("ldmatrix.sync.aligned.m8n8.x4.shared.b16 {%0,%1,%2,%3},[%4];" \
                 : "=r"(R0), "=r"(R1), "=r"(R2), "=r"(R3) : "r"(ADDR))
#define MMA16816(C, A, B0, B1)                                               \
    asm volatile("mma.sync.aligned.m16n8k16.row.col.f32.f16.f16.f32 "        \
                 "{%0,%1,%2,%3},{%4,%5,%6,%7},{%8,%9},{%0,%1,%2,%3};"        \
                 : "+f"((C)[0]), "+f"((C)[1]), "+f"((C)[2]), "+f"((C)[3])    \
                 : "r"((A)[0]), "r"((A)[1]), "r"((A)[2]), "r"((A)[3]),       \
                   "r"(B0), "r"(B1))

__device__ __forceinline__ __half2 split_pair(float a, float b, __half2& lo) {
    __half ah = __float2half_rn(a), bh = __float2half_rn(b);
    lo = __halves2half2(__float2half_rn(a - __half2float(ah)),
                        __float2half_rn(b - __half2float(bh)));
    return __halves2half2(ah, bh);
}

// ---------------------------------------------------------------------------
__global__ void cvt_h(const float* __restrict__ in, __half* __restrict__ hi, int n) {
    int i = blockIdx.x * blockDim.x + threadIdx.x;
    if (i >= n) return;
    hi[i] = __float2half_rn(in[i]);
}

// ---------------------------------------------------------------------------
__global__ void transpose_split_v(const float* __restrict__ V,
                                  __half* __restrict__ Vth,
                                  __half* __restrict__ Vtl) {
    __shared__ float tile[32][33];
    const int s0 = blockIdx.x * 32, d0 = blockIdx.y * 32;
    const int tx = threadIdx.x, ty = threadIdx.y;
#pragma unroll
    for (int i = 0; i < 4; i++)
        tile[ty + 8 * i][tx] = V[(size_t)(s0 + ty + 8 * i) * KV_D + d0 + tx];
    __syncthreads();
#pragma unroll
    for (int i = 0; i < 4; i++) {
        int d = d0 + ty + 8 * i, s = s0 + tx;
        float v = tile[tx][ty + 8 * i];
        __half h = __float2half_rn(v);
        Vth[(size_t)d * S_LEN + s] = h;
        Vtl[(size_t)d * S_LEN + s] = __float2half_rn(v - __half2float(h));
    }
}

// ---------------------------------------------------------------------------
// HGEMM: C = A @ Bh^T (TERMS=1: A=Ah; TERMS=2: A=Ah+Al), fp32 accum.
// MODE 0: fp32 C out. MODE 1: rope+scale+split-fp16 out.
// 128x128 tile, k32, 3-stage cp.async ring, 256 threads, 2 CTAs/SM.
// ---------------------------------------------------------------------------
#define HGEMM_SMEM (3 * 32768)

template<int MODE, int TERMS>
__global__ __launch_bounds__(256, 2)
void hgemm_split(const __half* __restrict__ Ah, const __half* __restrict__ Al,
                 const __half* __restrict__ Bh,
                 float* __restrict__ C,
                 __half* __restrict__ Hi, __half* __restrict__ Lo,
                 const float* __restrict__ cosw, const float* __restrict__ sinw,
                 float scale, int M, int N, int K) {
    extern __shared__ __half smh[];
    const uint32_t sbase = (uint32_t)__cvta_generic_to_shared(smh);

    const int t    = threadIdx.x;
    const int m0   = blockIdx.y * 128;
    const int n0   = blockIdx.x * 128;
    const int warp = t >> 5;
    const int lane = t & 31;
    const int wm   = (warp >> 1) * 32;
    const int wn   = (warp & 1) * 64;

    const int a_mloc = lane & 15;
    const int a_gsel = lane >> 4;
    const int b_nloc = (lane & 7) + ((lane & 16) >> 1);
    const int b_gsel = (lane >> 3) & 1;

    float acc[2][8][4];
#pragma unroll
    for (int mt = 0; mt < 2; mt++)
#pragma unroll
        for (int nt = 0; nt < 8; nt++)
#pragma unroll
            for (int r = 0; r < 4; r++) acc[mt][nt][r] = 0.f;

    auto issue = [&](int k0, int buf) {
        uint32_t abase = sbase + buf * 32768;
        uint32_t bbase = abase + 16384;
        const int AIT = (TERMS == 2) ? 4 : 2;
#pragma unroll
        for (int i = 0; i < 4; i++) {
            if (i >= AIT) break;
            int ga = t + i * 256;
            int m, sg;
            if (TERMS == 2) { m = ga >> 3; sg = ga & 7; }
            else            { m = ga >> 2; sg = ga & 3; }
            const __half* src = ((TERMS == 2 && sg >= 4) ? Al : Ah)
                              + (size_t)(m0 + m) * K + k0 + (sg & 3) * 8;
            cp16(abase + m * 128 + ((sg ^ (m & 7)) << 4), src);
        }
#pragma unroll
        for (int i = 0; i < 2; i++) {
            int ga = t + i * 256;
            int n = ga >> 2, sg = ga & 3;
            const __half* src = Bh + (size_t)(n0 + n) * K + k0 + sg * 8;
            cp16(bbase + n * 128 + ((sg ^ (n & 7)) << 4), src);
        }
    };

    const int NIT = K >> 5;
    issue(0, 0);
    asm volatile("cp.async.commit_group;");
    issue(32, 1);
    asm volatile("cp.async.commit_group;");

    for (int it = 0; it < NIT; it++) {
        if (it + 2 < NIT) {
            issue((it + 2) << 5, (it + 2) % 3);
            asm volatile("cp.async.commit_group;");
            asm volatile("cp.async.wait_group 2;");
        } else if (it + 1 < NIT) {
            asm volatile("cp.async.wait_group 1;");
        } else {
            asm volatile("cp.async.wait_group 0;");
        }
        __syncthreads();

        const uint32_t abase = sbase + (it % 3) * 32768;
        const uint32_t bbase = abase + 16384;

#pragma unroll
        for (int c = 0; c < 2; c++) {
            uint32_t ah[2][4], bb[4][4];
#pragma unroll
            for (int mt = 0; mt < 2; mt++) {
                int m = wm + mt * 16 + a_mloc;
                int sg = 2 * c + a_gsel;
                LDSM4(ah[mt][0], ah[mt][1], ah[mt][2], ah[mt][3],
                      abase + m * 128 + ((sg ^ (m & 7)) << 4));
            }
#pragma unroll
            for (int p = 0; p < 4; p++) {
                int n = wn + p * 16 + b_nloc;
                int sg = 2 * c + b_gsel;
                LDSM4(bb[p][0], bb[p][1], bb[p][2], bb[p][3],
                      bbase + n * 128 + ((sg ^ (n & 7)) << 4));
            }
#pragma unroll
            for (int mt = 0; mt < 2; mt++)
#pragma unroll
                for (int p = 0; p < 4; p++) {
                    MMA16816(acc[mt][2 * p],     ah[mt], bb[p][0], bb[p][1]);
                    MMA16816(acc[mt][2 * p + 1], ah[mt], bb[p][2], bb[p][3]);
                }
            if (TERMS == 2) {
                uint32_t al[2][4];
#pragma unroll
                for (int mt = 0; mt < 2; mt++) {
                    int m = wm + mt * 16 + a_mloc;
                    int sg = 4 + 2 * c + a_gsel;
                    LDSM4(al[mt][0], al[mt][1], al[mt][2], al[mt][3],
                          abase + m * 128 + ((sg ^ (m & 7)) << 4));
                }
#pragma unroll
                for (int mt = 0; mt < 2; mt++)
#pragma unroll
                    for (int p = 0; p < 4; p++) {
                        MMA16816(acc[mt][2 * p],     al[mt], bb[p][0], bb[p][1]);
                        MMA16816(acc[mt][2 * p + 1], al[mt], bb[p][2], bb[p][3]);
                    }
            }
        }
        __syncthreads();
    }

    // ---- epilogue ----
#pragma unroll
    for (int mt = 0; mt < 2; mt++) {
        int r = m0 + wm + mt * 16 + (lane >> 2);
#pragma unroll
        for (int nt = 0; nt < 8; nt++) {
            int cc = n0 + wn + nt * 8 + (lane & 3) * 2;
            if (MODE == 0) {
                float* p0 = C + (size_t)r * N + cc;
                p0[0] = acc[mt][nt][0];
                p0[1] = acc[mt][nt][1];
                float* p1 = p0 + 8 * N;
                p1[0] = acc[mt][nt][2];
                p1[1] = acc[mt][nt][3];
            } else {
                int i = (cc & 127) >> 1;
                {
                    float cw = cosw[r * 64 + i], sw = sinw[r * 64 + i];
                    float t0 = acc[mt][nt][0], t1 = acc[mt][nt][1];
                    float r0 = (t0 * cw - t1 * sw) * scale;
                    float r1 = (t0 * sw + t1 * cw) * scale;
                    __half2 lo2, hi2 = split_pair(r0, r1, lo2);
                    *(__half2*)(Hi + (size_t)r * N + cc) = hi2;
                    *(__half2*)(Lo + (size_t)r * N + cc) = lo2;
                }
                {
                    int r8 = r + 8;
                    float cw = cosw[r8 * 64 + i], sw = sinw[r8 * 64 + i];
                    float t0 = acc[mt][nt][2], t1 = acc[mt][nt][3];
                    float r0 = (t0 * cw - t1 * sw) * scale;
                    float r1 = (t0 * sw + t1 * cw) * scale;
                    __half2 lo2, hi2 = split_pair(r0, r1, lo2);
                    *(__half2*)(Hi + (size_t)r8 * N + cc) = hi2;
                    *(__half2*)(Lo + (size_t)r8 * N + cc) = lo2;
                }
            }
        }
    }
}

// ---------------------------------------------------------------------------
// Flash attention on tensor cores (split-fp16, 3-term), fp16 output (hi only).
// Single-buffered (96KB smem).
// ---------------------------------------------------------------------------
#define FQ_OFF  0
#define FK_OFF  32768
#define FV_OFF  65536
#define FLASH_TC_SMEM 98304

__global__ __launch_bounds__(128, 1)
void flash_tc(const __half* __restrict__ Qh, const __half* __restrict__ Ql,
              const __half* __restrict__ Kh, const __half* __restrict__ Kl,
              const __half* __restrict__ Vth, const __half* __restrict__ Vtl,
              __half* __restrict__ Oh) {
    extern __shared__ char smc[];
    const uint32_t sb = (uint32_t)__cvta_generic_to_shared(smc);
    const int t    = threadIdx.x;
    const int lane = t & 31;
    const int warp = t >> 5;
    const int qt   = (int)gridDim.x - 1 - (int)blockIdx.x;
    const int h    = blockIdx.y;
    const int kh   = h >> 2;
    const int q0   = qt * 64;

    const int a_ml = lane & 15;
    const int a_gs = lane >> 4;
    const int b_nl = (lane & 7) + ((lane & 16) >> 1);
    const int b_gs = (lane >> 3) & 1;

#pragma unroll
    for (int i = 0; i < 16; i++) {
        int g = t + i * 128;
        int hf = g >> 10, gg = g & 1023;
        int r = gg >> 4, c = gg & 15;
        const __half* src = (hf ? Ql : Qh)
                          + (size_t)(q0 + r) * D_MODEL + h * HDIM + c * 8;
        cp16(sb + FQ_OFF + hf * 16384 + r * 256 + ((c ^ (r & 7)) << 4), src);
    }
    asm volatile("cp.async.commit_group;");

    float o[16][4];
#pragma unroll
    for (int nt = 0; nt < 16; nt++)
#pragma unroll
        for (int j = 0; j < 4; j++) o[nt][j] = 0.f;
    float m0r = -1e30f, m1r = -1e30f, l0 = 0.f, l1 = 0.f;

    for (int kt = 0; kt <= qt; kt++) {
        const int k0 = kt * 64;
        __syncthreads();
#pragma unroll
        for (int i = 0; i < 16; i++) {
            int g = t + i * 128;
            int hf = g >> 10, gg = g & 1023;
            int r = gg >> 4, c = gg & 15;
            const __half* src = (hf ? Kl : Kh)
                              + (size_t)(k0 + r) * KV_D + kh * HDIM + c * 8;
            cp16(sb + FK_OFF + hf * 16384 + r * 256 + ((c ^ (r & 7)) << 4), src);
        }
#pragma unroll
        for (int i = 0; i < 16; i++) {
            int g = t + i * 128;
            int hf = g >> 10, gg = g & 1023;
            int r = gg >> 3, c = gg & 7;
            const __half* src = (hf ? Vtl : Vth)
                              + (size_t)(kh * HDIM + r) * S_LEN + k0 + c * 8;
            cp16(sb + FV_OFF + hf * 16384 + r * 128 + ((c ^ (r & 7)) << 4), src);
        }
        asm volatile("cp.async.commit_group;");
        asm volatile("cp.async.wait_group 0;");
        __syncthreads();

        float sacc[8][4];
#pragma unroll
        for (int nt = 0; nt < 8; nt++)
#pragma unroll
            for (int j = 0; j < 4; j++) sacc[nt][j] = 0.f;

#pragma unroll
        for (int kc = 0; kc < 8; kc++) {
            uint32_t aqh[4], aql[4];
            {
                int r = warp * 16 + a_ml;
                int cf = 2 * kc + a_gs;
                uint32_t qa = sb + FQ_OFF + r * 256 + ((cf ^ (r & 7)) << 4);
                LDSM4(aqh[0], aqh[1], aqh[2], aqh[3], qa);
                LDSM4(aql[0], aql[1], aql[2], aql[3], qa + 16384);
            }
#pragma unroll
            for (int p = 0; p < 4; p++) {
                int n = p * 16 + b_nl;
                int cf = 2 * kc + b_gs;
                uint32_t ka = sb + FK_OFF + n * 256 + ((cf ^ (n & 7)) << 4);
                uint32_t bh[4], bl[4];
                LDSM4(bh[0], bh[1], bh[2], bh[3], ka);
                LDSM4(bl[0], bl[1], bl[2], bl[3], ka + 16384);
                MMA16816(sacc[2 * p],     aqh, bh[0], bh[1]);
                MMA16816(sacc[2 * p + 1], aqh, bh[2], bh[3]);
                MMA16816(sacc[2 * p],     aqh, bl[0], bl[1]);
                MMA16816(sacc[2 * p + 1], aqh, bl[2], bl[3]);
                MMA16816(sacc[2 * p],     aql, bh[0], bh[1]);
                MMA16816(sacc[2 * p + 1], aql, bh[2], bh[3]);
            }
        }

        if (kt == qt) {
            int rg0 = q0 + warp * 16 + (lane >> 2);
#pragma unroll
            for (int nt = 0; nt < 8; nt++) {
                int cg = k0 + nt * 8 + (lane & 3) * 2;
                if (cg     > rg0)     sacc[nt][0] += -1e9f;
                if (cg + 1 > rg0)     sacc[nt][1] += -1e9f;
                if (cg     > rg0 + 8) sacc[nt][2] += -1e9f;
                if (cg + 1 > rg0 + 8) sacc[nt][3] += -1e9f;
            }
        }

        float rmax0 = -1e30f, rmax1 = -1e30f;
#pragma unroll
        for (int nt = 0; nt < 8; nt++) {
            rmax0 = fmaxf(rmax0, fmaxf(sacc[nt][0], sacc[nt][1]));
            rmax1 = fmaxf(rmax1, fmaxf(sacc[nt][2], sacc[nt][3]));
        }
#pragma unroll
        for (int off = 1; off < 4; off <<= 1) {
            rmax0 = fmaxf(rmax0, __shfl_xor_sync(0xffffffffu, rmax0, off));
            rmax1 = fmaxf(rmax1, __shfl_xor_sync(0xffffffffu, rmax1, off));
        }
        float mn0 = fmaxf(m0r, rmax0), mn1 = fmaxf(m1r, rmax1);
        float al0 = __expf(m0r - mn0), al1 = __expf(m1r - mn1);
        m0r = mn0; m1r = mn1;

        float rs0 = 0.f, rs1 = 0.f;
#pragma unroll
        for (int nt = 0; nt < 8; nt++) {
            sacc[nt][0] = __expf(sacc[nt][0] - mn0);
            sacc[nt][1] = __expf(sacc[nt][1] - mn0);
            sacc[nt][2] = __expf(sacc[nt][2] - mn1);
            sacc[nt][3] = __expf(sacc[nt][3] - mn1);
            rs0 += sacc[nt][0] + sacc[nt][1];
            rs1 += sacc[nt][2] + sacc[nt][3];
        }
#pragma unroll
        for (int off = 1; off < 4; off <<= 1) {
            rs0 += __shfl_xor_sync(0xffffffffu, rs0, off);
            rs1 += __shfl_xor_sync(0xffffffffu, rs1, off);
        }
        l0 = l0 * al0 + rs0;
        l1 = l1 * al1 + rs1;
#pragma unroll
        for (int nt = 0; nt < 16; nt++) {
            o[nt][0] *= al0; o[nt][1] *= al0;
            o[nt][2] *= al1; o[nt][3] *= al1;
        }

#pragma unroll
        for (int kc = 0; kc < 4; kc++) {
            uint32_t ph[4], pl[4];
            {
                __half2 l2;
                __half2 h2 = split_pair(sacc[2*kc][0], sacc[2*kc][1], l2);
                ph[0] = *(uint32_t*)&h2; pl[0] = *(uint32_t*)&l2;
                h2 = split_pair(sacc[2*kc][2], sacc[2*kc][3], l2);
                ph[1] = *(uint32_t*)&h2; pl[1] = *(uint32_t*)&l2;
                h2 = split_pair(sacc[2*kc+1][0], sacc[2*kc+1][1], l2);
                ph[2] = *(uint32_t*)&h2; pl[2] = *(uint32_t*)&l2;
                h2 = split_pair(sacc[2*kc+1][2], sacc[2*kc+1][3], l2);
                ph[3] = *(uint32_t*)&h2; pl[3] = *(uint32_t*)&l2;
            }
#pragma unroll
            for (int p = 0; p < 8; p++) {
                int n = p * 16 + b_nl;
                int cf = 2 * kc + b_gs;
                uint32_t va = sb + FV_OFF + n * 128 + ((cf ^ (n & 7)) << 4);
                uint32_t bh[4], bl[4];
                LDSM4(bh[0], bh[1], bh[2], bh[3], va);
                LDSM4(bl[0], bl[1], bl[2], bl[3], va + 16384);
                MMA16816(o[2 * p],     ph, bh[0], bh[1]);
                MMA16816(o[2 * p + 1], ph, bh[2], bh[3]);
                MMA16816(o[2 * p],     ph, bl[0], bl[1]);
                MMA16816(o[2 * p + 1], ph, bl[2], bl[3]);
                MMA16816(o[2 * p],     pl, bh[0], bh[1]);
                MMA16816(o[2 * p + 1], pl, bh[2], bh[3]);
            }
        }
    }

    // ---- epilogue: normalize, plain fp16 out ----
    float inv0 = 1.f / l0, inv1 = 1.f / l1;
    int rg0 = q0 + warp * 16 + (lane >> 2);
#pragma unroll
    for (int nt = 0; nt < 16; nt++) {
        int col = h * HDIM + nt * 8 + (lane & 3) * 2;
        *(__half2*)(Oh + (size_t)rg0 * D_MODEL + col) =
            __halves2half2(__float2half_rn(o[nt][0] * inv0),
                           __float2half_rn(o[nt][1] * inv0));
        *(__half2*)(Oh + (size_t)(rg0 + 8) * D_MODEL + col) =
            __halves2half2(__float2half_rn(o[nt][2] * inv1),
                           __float2half_rn(o[nt][3] * inv1));
    }
}

// ---------------------------------------------------------------------------
extern "C" void kernel_launch(void* const* d_in, const int* in_sizes, int n_in,
                              void* d_out, int out_size) {
    const float* x  = (const float*)d_in[0];
    const float* fc = (const float*)d_in[1];
    const float* fs = (const float*)d_in[2];
    const float* wq = (const float*)d_in[4];
    const float* wk = (const float*)d_in[5];
    const float* wv = (const float*)d_in[6];
    const float* wo = (const float*)d_in[7];
    float* out = (float*)d_out;

    float* vp;
    cudaGetSymbolAddress((void**)&vp, g_V);

    __half *xh, *wqh, *wkh, *wvh, *woh, *ah;
    __half *qfh, *qfl, *kfh, *kfl, *vth, *vtl;
    cudaGetSymbolAddress((void**)&xh,  g_xh);
    cudaGetSymbolAddress((void**)&wqh, g_wqh);
    cudaGetSymbolAddress((void**)&wkh, g_wkh);
    cudaGetSymbolAddress((void**)&wvh, g_wvh);
    cudaGetSymbolAddress((void**)&woh, g_woh);
    cudaGetSymbolAddress((void**)&ah,  g_ah);
    cudaGetSymbolAddress((void**)&qfh, g_Qfh); cudaGetSymbolAddress((void**)&qfl, g_Qfl);
    cudaGetSymbolAddress((void**)&kfh, g_Kfh); cudaGetSymbolAddress((void**)&kfl, g_Kfl);
    cudaGetSymbolAddress((void**)&vth, g_Vth); cudaGetSymbolAddress((void**)&vtl, g_Vtl);

    cudaFuncSetAttribute((const void*)hgemm_split<0, 1>,
                         cudaFuncAttributeMaxDynamicSharedMemorySize, HGEMM_SMEM);
    cudaFuncSetAttribute((const void*)hgemm_split<1, 1>,
                         cudaFuncAttributeMaxDynamicSharedMemorySize, HGEMM_SMEM);
    cudaFuncSetAttribute((const void*)flash_tc,
                         cudaFuncAttributeMaxDynamicSharedMemorySize, FLASH_TC_SMEM);

    const int NX  = S_LEN * D_MODEL;
    const int NW  = D_MODEL * D_MODEL;
    const int NKW = KV_D * D_MODEL;

    cvt_h<<<(NX  + 255) / 256, 256>>>(x,  xh,  NX);
    cvt_h<<<(NW  + 255) / 256, 256>>>(wq, wqh, NW);
    cvt_h<<<(NKW + 255) / 256, 256>>>(wk, wkh, NKW);
    cvt_h<<<(NKW + 255) / 256, 256>>>(wv, wvh, NKW);
    cvt_h<<<(NW  + 255) / 256, 256>>>(wo, woh, NW);

    // Q/K projections (1-term), fused rope+scale+split epilogue
    hgemm_split<1, 1><<<dim3(32, 16), 256, HGEMM_SMEM>>>(
        xh, nullptr, wqh, nullptr, qfh, qfl, fc, fs, ATT_SCALE,
        S_LEN, NH * HDIM, D_MODEL);
    hgemm_split<1, 1><<<dim3(8, 16), 256, HGEMM_SMEM>>>(
        xh, nullptr, wkh, nullptr, kfh, kfl, fc, fs, 1.f,
        S_LEN, KV_D, D_MODEL);
    // V projection (1-term) + transpose/split
    hgemm_split<0, 1><<<dim3(8, 16), 256, HGEMM_SMEM>>>(
        xh, nullptr, wvh, vp, nullptr, nullptr, nullptr, nullptr, 1.f,
        S_LEN, KV_D, D_MODEL);
    transpose_split_v<<<dim3(S_LEN / 32, KV_D / 32), dim3(32, 8)>>>(vp, vth, vtl);

    // Flash attention (tensor cores, 3-term), fp16 out
    flash_tc<<<dim3(32, 32), 128, FLASH_TC_SMEM>>>(qfh, qfl, kfh, kfl, vth, vtl, ah);

    // Output projection (1-term)
    hgemm_split<0, 1><<<dim3(32, 16), 256, HGEMM_SMEM>>>(
        ah, nullptr, woh, out, nullptr, nullptr, nullptr, nullptr, 1.f,
        S_LEN, D_MODEL, D_MODEL);
}

// round 15
// speedup vs baseline: 1.6181x; 1.0853x over previous
#include <cuda_runtime.h>
#include <cuda_fp16.h>
#include <math.h>
#include <stdint.h>

#define S_LEN   2048
#define D_MODEL 4096
#define NH      32
#define NKV     8
#define HDIM    128
#define KV_D    (NKV * HDIM)           // 1024
#define ATT_SCALE 0.08838834764831843f // 128^-0.5

// ---------------- static scratch (allocation forbidden) --------------------
__device__ float g_V[S_LEN * KV_D];

__device__ __half g_xh[S_LEN * D_MODEL];
__device__ __half g_wqh[D_MODEL * D_MODEL];
__device__ __half g_wkh[KV_D * D_MODEL];
__device__ __half g_wvh[KV_D * D_MODEL];
__device__ __half g_woh[D_MODEL * D_MODEL];
__device__ __half g_ah[S_LEN * D_MODEL];

__device__ __half g_Qfh[S_LEN * D_MODEL];                          // rope'd, scaled
__device__ __half g_Kfh[S_LEN * KV_D],    g_Kfl[S_LEN * KV_D];     // rope'd, split
__device__ __half g_Vth[KV_D * S_LEN],    g_Vtl[KV_D * S_LEN];     // [kvh*128+d][s]

// ---------------------------------------------------------------------------
__device__ __forceinline__ void cp16(uint32_t dst, const void* src) {
    asm volatile("cp.async.cg.shared.global [%0], [%1], 16;\n" :: "r"(dst), "l"(src));
}
#define LDSM4(R0, R1, R2, R3, ADDR)                                          \
    asm volatile("ldmatrix.sync.aligned.m8n8.x4.shared.b16 {%0,%1,%2,%3},[%4];" \
                 : "=r"(R0), "=r"(R1), "=r"(R2), "=r"(R3) : "r"(ADDR))
#define MMA16816(C, A, B0, B1)                                               \
    asm volatile("mma.sync.aligned.m16n8k16.row.col.f32.f16.f16.f32 "        \
                 "{%0,%1,%2,%3},{%4,%5,%6,%7},{%8,%9},{%0,%1,%2,%3};"        \
                 : "+f"((C)[0]), "+f"((C)[1]), "+f"((C)[2]), "+f"((C)[3])    \
                 : "r"((A)[0]), "r"((A)[1]), "r"((A)[2]), "r"((A)[3]),       \
                   "r"(B0), "r"(B1))

__device__ __forceinline__ __half2 split_pair(float a, float b, __half2& lo) {
    __half ah = __float2half_rn(a), bh = __float2half_rn(b);
    lo = __halves2half2(__float2half_rn(a - __half2float(ah)),
                        __float2half_rn(b - __half2float(bh)));
    return __halves2half2(ah, bh);
}

// ---------------------------------------------------------------------------
__global__ void cvt_h(const float* __restrict__ in, __half* __restrict__ hi, int n) {
    int i = blockIdx.x * blockDim.x + threadIdx.x;
    if (i >= n) return;
    hi[i] = __float2half_rn(in[i]);
}

// ---------------------------------------------------------------------------
__global__ void transpose_split_v(const float* __restrict__ V,
                                  __half* __restrict__ Vth,
                                  __half* __restrict__ Vtl) {
    __shared__ float tile[32][33];
    const int s0 = blockIdx.x * 32, d0 = blockIdx.y * 32;
    const int tx = threadIdx.x, ty = threadIdx.y;
#pragma unroll
    for (int i = 0; i < 4; i++)
        tile[ty + 8 * i][tx] = V[(size_t)(s0 + ty + 8 * i) * KV_D + d0 + tx];
    __syncthreads();
#pragma unroll
    for (int i = 0; i < 4; i++) {
        int d = d0 + ty + 8 * i, s = s0 + tx;
        float v = tile[tx][ty + 8 * i];
        __half h = __float2half_rn(v);
        Vth[(size_t)d * S_LEN + s] = h;
        Vtl[(size_t)d * S_LEN + s] = __float2half_rn(v - __half2float(h));
    }
}

// ---------------------------------------------------------------------------
// HGEMM: C = A @ Bh^T (TERMS=1: A=Ah; TERMS=2: A=Ah+Al), fp32 accum.
// MODE 0: fp32 C out. MODE 1: rope+scale+split-fp16 (hi+lo). MODE 2: rope+scale hi-only.
// 128x128 tile, k32, 3-stage cp.async ring, 256 threads, 2 CTAs/SM.
// ---------------------------------------------------------------------------
#define HGEMM_SMEM (3 * 32768)

template<int MODE, int TERMS>
__global__ __launch_bounds__(256, 2)
void hgemm_split(const __half* __restrict__ Ah, const __half* __restrict__ Al,
                 const __half* __restrict__ Bh,
                 float* __restrict__ C,
                 __half* __restrict__ Hi, __half* __restrict__ Lo,
                 const float* __restrict__ cosw, const float* __restrict__ sinw,
                 float scale, int M, int N, int K) {
    extern __shared__ __half smh[];
    const uint32_t sbase = (uint32_t)__cvta_generic_to_shared(smh);

    const int t    = threadIdx.x;
    const int m0   = blockIdx.y * 128;
    const int n0   = blockIdx.x * 128;
    const int warp = t >> 5;
    const int lane = t & 31;
    const int wm   = (warp >> 1) * 32;
    const int wn   = (warp & 1) * 64;

    const int a_mloc = lane & 15;
    const int a_gsel = lane >> 4;
    const int b_nloc = (lane & 7) + ((lane & 16) >> 1);
    const int b_gsel = (lane >> 3) & 1;

    float acc[2][8][4];
#pragma unroll
    for (int mt = 0; mt < 2; mt++)
#pragma unroll
        for (int nt = 0; nt < 8; nt++)
#pragma unroll
            for (int r = 0; r < 4; r++) acc[mt][nt][r] = 0.f;

    auto issue = [&](int k0, int buf) {
        uint32_t abase = sbase + buf * 32768;
        uint32_t bbase = abase + 16384;
        const int AIT = (TERMS == 2) ? 4 : 2;
#pragma unroll
        for (int i = 0; i < 4; i++) {
            if (i >= AIT) break;
            int ga = t + i * 256;
            int m, sg;
            if (TERMS == 2) { m = ga >> 3; sg = ga & 7; }
            else            { m = ga >> 2; sg = ga & 3; }
            const __half* src = ((TERMS == 2 && sg >= 4) ? Al : Ah)
                              + (size_t)(m0 + m) * K + k0 + (sg & 3) * 8;
            cp16(abase + m * 128 + ((sg ^ (m & 7)) << 4), src);
        }
#pragma unroll
        for (int i = 0; i < 2; i++) {
            int ga = t + i * 256;
            int n = ga >> 2, sg = ga & 3;
            const __half* src = Bh + (size_t)(n0 + n) * K + k0 + sg * 8;
            cp16(bbase + n * 128 + ((sg ^ (n & 7)) << 4), src);
        }
    };

    const int NIT = K >> 5;
    issue(0, 0);
    asm volatile("cp.async.commit_group;");
    issue(32, 1);
    asm volatile("cp.async.commit_group;");

    for (int it = 0; it < NIT; it++) {
        if (it + 2 < NIT) {
            issue((it + 2) << 5, (it + 2) % 3);
            asm volatile("cp.async.commit_group;");
            asm volatile("cp.async.wait_group 2;");
        } else if (it + 1 < NIT) {
            asm volatile("cp.async.wait_group 1;");
        } else {
            asm volatile("cp.async.wait_group 0;");
        }
        __syncthreads();

        const uint32_t abase = sbase + (it % 3) * 32768;
        const uint32_t bbase = abase + 16384;

#pragma unroll
        for (int c = 0; c < 2; c++) {
            uint32_t ah[2][4], bb[4][4];
#pragma unroll
            for (int mt = 0; mt < 2; mt++) {
                int m = wm + mt * 16 + a_mloc;
                int sg = 2 * c + a_gsel;
                LDSM4(ah[mt][0], ah[mt][1], ah[mt][2], ah[mt][3],
                      abase + m * 128 + ((sg ^ (m & 7)) << 4));
            }
#pragma unroll
            for (int p = 0; p < 4; p++) {
                int n = wn + p * 16 + b_nloc;
                int sg = 2 * c + b_gsel;
                LDSM4(bb[p][0], bb[p][1], bb[p][2], bb[p][3],
                      bbase + n * 128 + ((sg ^ (n & 7)) << 4));
            }
#pragma unroll
            for (int mt = 0; mt < 2; mt++)
#pragma unroll
                for (int p = 0; p < 4; p++) {
                    MMA16816(acc[mt][2 * p],     ah[mt], bb[p][0], bb[p][1]);
                    MMA16816(acc[mt][2 * p + 1], ah[mt], bb[p][2], bb[p][3]);
                }
            if (TERMS == 2) {
                uint32_t al[2][4];
#pragma unroll
                for (int mt = 0; mt < 2; mt++) {
                    int m = wm + mt * 16 + a_mloc;
                    int sg = 4 + 2 * c + a_gsel;
                    LDSM4(al[mt][0], al[mt][1], al[mt][2], al[mt][3],
                          abase + m * 128 + ((sg ^ (m & 7)) << 4));
                }
#pragma unroll
                for (int mt = 0; mt < 2; mt++)
#pragma unroll
                    for (int p = 0; p < 4; p++) {
                        MMA16816(acc[mt][2 * p],     al[mt], bb[p][0], bb[p][1]);
                        MMA16816(acc[mt][2 * p + 1], al[mt], bb[p][2], bb[p][3]);
                    }
            }
        }
        __syncthreads();
    }

    // ---- epilogue ----
#pragma unroll
    for (int mt = 0; mt < 2; mt++) {
        int r = m0 + wm + mt * 16 + (lane >> 2);
#pragma unroll
        for (int nt = 0; nt < 8; nt++) {
            int cc = n0 + wn + nt * 8 + (lane & 3) * 2;
            if (MODE == 0) {
                float* p0 = C + (size_t)r * N + cc;
                p0[0] = acc[mt][nt][0];
                p0[1] = acc[mt][nt][1];
                float* p1 = p0 + 8 * N;
                p1[0] = acc[mt][nt][2];
                p1[1] = acc[mt][nt][3];
            } else {
                int i = (cc & 127) >> 1;
                {
                    float cw = cosw[r * 64 + i], sw = sinw[r * 64 + i];
                    float t0 = acc[mt][nt][0], t1 = acc[mt][nt][1];
                    float r0 = (t0 * cw - t1 * sw) * scale;
                    float r1 = (t0 * sw + t1 * cw) * scale;
                    if (MODE == 1) {
                        __half2 lo2, hi2 = split_pair(r0, r1, lo2);
                        *(__half2*)(Hi + (size_t)r * N + cc) = hi2;
                        *(__half2*)(Lo + (size_t)r * N + cc) = lo2;
                    } else {
                        *(__half2*)(Hi + (size_t)r * N + cc) =
                            __halves2half2(__float2half_rn(r0), __float2half_rn(r1));
                    }
                }
                {
                    int r8 = r + 8;
                    float cw = cosw[r8 * 64 + i], sw = sinw[r8 * 64 + i];
                    float t0 = acc[mt][nt][2], t1 = acc[mt][nt][3];
                    float r0 = (t0 * cw - t1 * sw) * scale;
                    float r1 = (t0 * sw + t1 * cw) * scale;
                    if (MODE == 1) {
                        __half2 lo2, hi2 = split_pair(r0, r1, lo2);
                        *(__half2*)(Hi + (size_t)r8 * N + cc) = hi2;
                        *(__half2*)(Lo + (size_t)r8 * N + cc) = lo2;
                    } else {
                        *(__half2*)(Hi + (size_t)r8 * N + cc) =
                            __halves2half2(__float2half_rn(r0), __float2half_rn(r1));
                    }
                }
            }
        }
    }
}

// ---------------------------------------------------------------------------
// Flash attention, 2-term: S = Qh·(Kh+Kl), O = Ph·(Vh+Vl). fp16 out.
// smem: Q(hi) 16KB | K hi+lo 32KB | V hi+lo 32KB = 80KB.
// ---------------------------------------------------------------------------
#define FQ_OFF  0
#define FK_OFF  16384
#define FV_OFF  49152
#define FLASH_TC_SMEM 81920

__global__ __launch_bounds__(128, 1)
void flash_tc(const __half* __restrict__ Qh,
              const __half* __restrict__ Kh, const __half* __restrict__ Kl,
              const __half* __restrict__ Vth, const __half* __restrict__ Vtl,
              __half* __restrict__ Oh) {
    extern __shared__ char smc[];
    const uint32_t sb = (uint32_t)__cvta_generic_to_shared(smc);
    const int t    = threadIdx.x;
    const int lane = t & 31;
    const int warp = t >> 5;
    const int qt   = (int)gridDim.x - 1 - (int)blockIdx.x;
    const int h    = blockIdx.y;
    const int kh   = h >> 2;
    const int q0   = qt * 64;

    const int a_ml = lane & 15;
    const int a_gs = lane >> 4;
    const int b_nl = (lane & 7) + ((lane & 16) >> 1);
    const int b_gs = (lane >> 3) & 1;

    // Q tile (hi only): 1024 granules, 8 per thread
#pragma unroll
    for (int i = 0; i < 8; i++) {
        int g = t + i * 128;
        int r = g >> 4, c = g & 15;
        const __half* src = Qh + (size_t)(q0 + r) * D_MODEL + h * HDIM + c * 8;
        cp16(sb + FQ_OFF + r * 256 + ((c ^ (r & 7)) << 4), src);
    }
    asm volatile("cp.async.commit_group;");

    float o[16][4];
#pragma unroll
    for (int nt = 0; nt < 16; nt++)
#pragma unroll
        for (int j = 0; j < 4; j++) o[nt][j] = 0.f;
    float m0r = -1e30f, m1r = -1e30f, l0 = 0.f, l1 = 0.f;

    for (int kt = 0; kt <= qt; kt++) {
        const int k0 = kt * 64;
        __syncthreads();
#pragma unroll
        for (int i = 0; i < 16; i++) {
            int g = t + i * 128;
            int hf = g >> 10, gg = g & 1023;
            int r = gg >> 4, c = gg & 15;
            const __half* src = (hf ? Kl : Kh)
                              + (size_t)(k0 + r) * KV_D + kh * HDIM + c * 8;
            cp16(sb + FK_OFF + hf * 16384 + r * 256 + ((c ^ (r & 7)) << 4), src);
        }
#pragma unroll
        for (int i = 0; i < 16; i++) {
            int g = t + i * 128;
            int hf = g >> 10, gg = g & 1023;
            int r = gg >> 3, c = gg & 7;
            const __half* src = (hf ? Vtl : Vth)
                              + (size_t)(kh * HDIM + r) * S_LEN + k0 + c * 8;
            cp16(sb + FV_OFF + hf * 16384 + r * 128 + ((c ^ (r & 7)) << 4), src);
        }
        asm volatile("cp.async.commit_group;");
        asm volatile("cp.async.wait_group 0;");
        __syncthreads();

        float sacc[8][4];
#pragma unroll
        for (int nt = 0; nt < 8; nt++)
#pragma unroll
            for (int j = 0; j < 4; j++) sacc[nt][j] = 0.f;

#pragma unroll
        for (int kc = 0; kc < 8; kc++) {
            uint32_t aqh[4];
            {
                int r = warp * 16 + a_ml;
                int cf = 2 * kc + a_gs;
                LDSM4(aqh[0], aqh[1], aqh[2], aqh[3],
                      sb + FQ_OFF + r * 256 + ((cf ^ (r & 7)) << 4));
            }
#pragma unroll
            for (int p = 0; p < 4; p++) {
                int n = p * 16 + b_nl;
                int cf = 2 * kc + b_gs;
                uint32_t ka = sb + FK_OFF + n * 256 + ((cf ^ (n & 7)) << 4);
                uint32_t bh[4], bl[4];
                LDSM4(bh[0], bh[1], bh[2], bh[3], ka);
                LDSM4(bl[0], bl[1], bl[2], bl[3], ka + 16384);
                MMA16816(sacc[2 * p],     aqh, bh[0], bh[1]);
                MMA16816(sacc[2 * p + 1], aqh, bh[2], bh[3]);
                MMA16816(sacc[2 * p],     aqh, bl[0], bl[1]);
                MMA16816(sacc[2 * p + 1], aqh, bl[2], bl[3]);
            }
        }

        if (kt == qt) {
            int rg0 = q0 + warp * 16 + (lane >> 2);
#pragma unroll
            for (int nt = 0; nt < 8; nt++) {
                int cg = k0 + nt * 8 + (lane & 3) * 2;
                if (cg     > rg0)     sacc[nt][0] += -1e9f;
                if (cg + 1 > rg0)     sacc[nt][1] += -1e9f;
                if (cg     > rg0 + 8) sacc[nt][2] += -1e9f;
                if (cg + 1 > rg0 + 8) sacc[nt][3] += -1e9f;
            }
        }

        float rmax0 = -1e30f, rmax1 = -1e30f;
#pragma unroll
        for (int nt = 0; nt < 8; nt++) {
            rmax0 = fmaxf(rmax0, fmaxf(sacc[nt][0], sacc[nt][1]));
            rmax1 = fmaxf(rmax1, fmaxf(sacc[nt][2], sacc[nt][3]));
        }
#pragma unroll
        for (int off = 1; off < 4; off <<= 1) {
            rmax0 = fmaxf(rmax0, __shfl_xor_sync(0xffffffffu, rmax0, off));
            rmax1 = fmaxf(rmax1, __shfl_xor_sync(0xffffffffu, rmax1, off));
        }
        float mn0 = fmaxf(m0r, rmax0), mn1 = fmaxf(m1r, rmax1);
        float al0 = __expf(m0r - mn0), al1 = __expf(m1r - mn1);
        m0r = mn0; m1r = mn1;

        float rs0 = 0.f, rs1 = 0.f;
#pragma unroll
        for (int nt = 0; nt < 8; nt++) {
            sacc[nt][0] = __expf(sacc[nt][0] - mn0);
            sacc[nt][1] = __expf(sacc[nt][1] - mn0);
            sacc[nt][2] = __expf(sacc[nt][2] - mn1);
            sacc[nt][3] = __expf(sacc[nt][3] - mn1);
            rs0 += sacc[nt][0] + sacc[nt][1];
            rs1 += sacc[nt][2] + sacc[nt][3];
        }
#pragma unroll
        for (int off = 1; off < 4; off <<= 1) {
            rs0 += __shfl_xor_sync(0xffffffffu, rs0, off);
            rs1 += __shfl_xor_sync(0xffffffffu, rs1, off);
        }
        l0 = l0 * al0 + rs0;
        l1 = l1 * al1 + rs1;
#pragma unroll
        for (int nt = 0; nt < 16; nt++) {
            o[nt][0] *= al0; o[nt][1] *= al0;
            o[nt][2] *= al1; o[nt][3] *= al1;
        }

#pragma unroll
        for (int kc = 0; kc < 4; kc++) {
            uint32_t ph[4];
            {
                __half2 h2;
                h2 = __halves2half2(__float2half_rn(sacc[2*kc][0]),
                                    __float2half_rn(sacc[2*kc][1]));
                ph[0] = *(uint32_t*)&h2;
                h2 = __halves2half2(__float2half_rn(sacc[2*kc][2]),
                                    __float2half_rn(sacc[2*kc][3]));
                ph[1] = *(uint32_t*)&h2;
                h2 = __halves2half2(__float2half_rn(sacc[2*kc+1][0]),
                                    __float2half_rn(sacc[2*kc+1][1]));
                ph[2] = *(uint32_t*)&h2;
                h2 = __halves2half2(__float2half_rn(sacc[2*kc+1][2]),
                                    __float2half_rn(sacc[2*kc+1][3]));
                ph[3] = *(uint32_t*)&h2;
            }
#pragma unroll
            for (int p = 0; p < 8; p++) {
                int n = p * 16 + b_nl;
                int cf = 2 * kc + b_gs;
                uint32_t va = sb + FV_OFF + n * 128 + ((cf ^ (n & 7)) << 4);
                uint32_t bh[4], bl[4];
                LDSM4(bh[0], bh[1], bh[2], bh[3], va);
                LDSM4(bl[0], bl[1], bl[2], bl[3], va + 16384);
                MMA16816(o[2 * p],     ph, bh[0], bh[1]);
                MMA16816(o[2 * p + 1], ph, bh[2], bh[3]);
                MMA16816(o[2 * p],     ph, bl[0], bl[1]);
                MMA16816(o[2 * p + 1], ph, bl[2], bl[3]);
            }
        }
    }

    // ---- epilogue: normalize, fp16 out ----
    float inv0 = 1.f / l0, inv1 = 1.f / l1;
    int rg0 = q0 + warp * 16 + (lane >> 2);
#pragma unroll
    for (int nt = 0; nt < 16; nt++) {
        int col = h * HDIM + nt * 8 + (lane & 3) * 2;
        *(__half2*)(Oh + (size_t)rg0 * D_MODEL + col) =
            __halves2half2(__float2half_rn(o[nt][0] * inv0),
                           __float2half_rn(o[nt][1] * inv0));
        *(__half2*)(Oh + (size_t)(rg0 + 8) * D_MODEL + col) =
            __halves2half2(__float2half_rn(o[nt][2] * inv1),
                           __float2half_rn(o[nt][3] * inv1));
    }
}

// ---------------------------------------------------------------------------
extern "C" void kernel_launch(void* const* d_in, const int* in_sizes, int n_in,
                              void* d_out, int out_size) {
    const float* x  = (const float*)d_in[0];
    const float* fc = (const float*)d_in[1];
    const float* fs = (const float*)d_in[2];
    const float* wq = (const float*)d_in[4];
    const float* wk = (const float*)d_in[5];
    const float* wv = (const float*)d_in[6];
    const float* wo = (const float*)d_in[7];
    float* out = (float*)d_out;

    float* vp;
    cudaGetSymbolAddress((void**)&vp, g_V);

    __half *xh, *wqh, *wkh, *wvh, *woh, *ah;
    __half *qfh, *kfh, *kfl, *vth, *vtl;
    cudaGetSymbolAddress((void**)&xh,  g_xh);
    cudaGetSymbolAddress((void**)&wqh, g_wqh);
    cudaGetSymbolAddress((void**)&wkh, g_wkh);
    cudaGetSymbolAddress((void**)&wvh, g_wvh);
    cudaGetSymbolAddress((void**)&woh, g_woh);
    cudaGetSymbolAddress((void**)&ah,  g_ah);
    cudaGetSymbolAddress((void**)&qfh, g_Qfh);
    cudaGetSymbolAddress((void**)&kfh, g_Kfh); cudaGetSymbolAddress((void**)&kfl, g_Kfl);
    cudaGetSymbolAddress((void**)&vth, g_Vth); cudaGetSymbolAddress((void**)&vtl, g_Vtl);

    cudaFuncSetAttribute((const void*)hgemm_split<0, 1>,
                         cudaFuncAttributeMaxDynamicSharedMemorySize, HGEMM_SMEM);
    cudaFuncSetAttribute((const void*)hgemm_split<1, 1>,
                         cudaFuncAttributeMaxDynamicSharedMemorySize, HGEMM_SMEM);
    cudaFuncSetAttribute((const void*)hgemm_split<2, 1>,
                         cudaFuncAttributeMaxDynamicSharedMemorySize, HGEMM_SMEM);
    cudaFuncSetAttribute((const void*)flash_tc,
                         cudaFuncAttributeMaxDynamicSharedMemorySize, FLASH_TC_SMEM);

    const int NX  = S_LEN * D_MODEL;
    const int NW  = D_MODEL * D_MODEL;
    const int NKW = KV_D * D_MODEL;

    cvt_h<<<(NX  + 255) / 256, 256>>>(x,  xh,  NX);
    cvt_h<<<(NW  + 255) / 256, 256>>>(wq, wqh, NW);
    cvt_h<<<(NKW + 255) / 256, 256>>>(wk, wkh, NKW);
    cvt_h<<<(NKW + 255) / 256, 256>>>(wv, wvh, NKW);
    cvt_h<<<(NW  + 255) / 256, 256>>>(wo, woh, NW);

    // Q projection (1-term), rope+scale, hi-only output
    hgemm_split<2, 1><<<dim3(32, 16), 256, HGEMM_SMEM>>>(
        xh, nullptr, wqh, nullptr, qfh, nullptr, fc, fs, ATT_SCALE,
        S_LEN, NH * HDIM, D_MODEL);
    // K projection (1-term), rope, split hi+lo output
    hgemm_split<1, 1><<<dim3(8, 16), 256, HGEMM_SMEM>>>(
        xh, nullptr, wkh, nullptr, kfh, kfl, fc, fs, 1.f,
        S_LEN, KV_D, D_MODEL);
    // V projection (1-term) + transpose/split
    hgemm_split<0, 1><<<dim3(8, 16), 256, HGEMM_SMEM>>>(
        xh, nullptr, wvh, vp, nullptr, nullptr, nullptr, nullptr, 1.f,
        S_LEN, KV_D, D_MODEL);
    transpose_split_v<<<dim3(S_LEN / 32, KV_D / 32), dim3(32, 8)>>>(vp, vth, vtl);

    // Flash attention (2-term), fp16 out
    flash_tc<<<dim3(32, 32), 128, FLASH_TC_SMEM>>>(qfh, kfh, kfl, vth, vtl, ah);

    // Output projection (1-term)
    hgemm_split<0, 1><<<dim3(32, 16), 256, HGEMM_SMEM>>>(
        ah, nullptr, woh, out, nullptr, nullptr, nullptr, nullptr, 1.f,
        S_LEN, D_MODEL, D_MODEL);
}

// round 16
// speedup vs baseline: 1.9738x; 1.2198x over previous
#include <cuda_runtime.h>
#include <cuda_fp16.h>
#include <math.h>
#include <stdint.h>

#define S_LEN   2048
#define D_MODEL 4096
#define NH      32
#define NKV     8
#define HDIM    128
#define KV_D    (NKV * HDIM)           // 1024
#define ATT_SCALE 0.08838834764831843f // 128^-0.5

// ---------------- static scratch (allocation forbidden) --------------------
__device__ __half g_xh[S_LEN * D_MODEL];
__device__ __half g_wqh[D_MODEL * D_MODEL];
__device__ __half g_wkh[KV_D * D_MODEL];
__device__ __half g_wvh[KV_D * D_MODEL];
__device__ __half g_woh[D_MODEL * D_MODEL];
__device__ __half g_ah[S_LEN * D_MODEL];

__device__ __half g_Qfh[S_LEN * D_MODEL];                          // rope'd, scaled
__device__ __half g_Kfh[S_LEN * KV_D],    g_Kfl[S_LEN * KV_D];     // rope'd, split
__device__ __half g_Vth[KV_D * S_LEN];                             // [d][s] fp16

// ---------------------------------------------------------------------------
__device__ __forceinline__ void cp16(uint32_t dst, const void* src) {
    asm volatile("cp.async.cg.shared.global [%0], [%1], 16;\n" :: "r"(dst), "l"(src));
}
#define LDSM4(R0, R1, R2, R3, ADDR)                                          \
    asm volatile("ldmatrix.sync.aligned.m8n8.x4.shared.b16 {%0,%1,%2,%3},[%4];" \
                 : "=r"(R0), "=r"(R1), "=r"(R2), "=r"(R3) : "r"(ADDR))
#define MMA16816(C, A, B0, B1)                                               \
    asm volatile("mma.sync.aligned.m16n8k16.row.col.f32.f16.f16.f32 "        \
                 "{%0,%1,%2,%3},{%4,%5,%6,%7},{%8,%9},{%0,%1,%2,%3};"        \
                 : "+f"((C)[0]), "+f"((C)[1]), "+f"((C)[2]), "+f"((C)[3])    \
                 : "r"((A)[0]), "r"((A)[1]), "r"((A)[2]), "r"((A)[3]),       \
                   "r"(B0), "r"(B1))

__device__ __forceinline__ __half2 split_pair(float a, float b, __half2& lo) {
    __half ah = __float2half_rn(a), bh = __float2half_rn(b);
    lo = __halves2half2(__float2half_rn(a - __half2float(ah)),
                        __float2half_rn(b - __half2float(bh)));
    return __halves2half2(ah, bh);
}

// ---------------------------------------------------------------------------
// single-launch vectorized fp32 -> fp16 conversion of x + all 4 weights
// ---------------------------------------------------------------------------
__device__ __forceinline__ void cvt4(const float4 a, __half* dst) {
    __half2 h0 = __floats2half2_rn(a.x, a.y);
    __half2 h1 = __floats2half2_rn(a.z, a.w);
    uint2 u = make_uint2(*(uint32_t*)&h0, *(uint32_t*)&h1);
    *(uint2*)dst = u;
}

__global__ void cvt_all(const float* __restrict__ x,
                        const float* __restrict__ wq, const float* __restrict__ wk,
                        const float* __restrict__ wv, const float* __restrict__ wo,
                        __half* __restrict__ xh, __half* __restrict__ wqh,
                        __half* __restrict__ wkh, __half* __restrict__ wvh,
                        __half* __restrict__ woh) {
    const int NX4  = S_LEN * D_MODEL / 4;
    const int NW4  = D_MODEL * D_MODEL / 4;
    const int NKW4 = KV_D * D_MODEL / 4;
    int i = blockIdx.x * blockDim.x + threadIdx.x;
    if (i < NW4) {
        cvt4(((const float4*)wq)[i], wqh + i * 4);
        cvt4(((const float4*)wo)[i], woh + i * 4);
    }
    if (i < NX4)  cvt4(((const float4*)x)[i],  xh  + i * 4);
    if (i < NKW4) {
        cvt4(((const float4*)wk)[i], wkh + i * 4);
        cvt4(((const float4*)wv)[i], wvh + i * 4);
    }
}

// ---------------------------------------------------------------------------
// HGEMM (1-term A): C = Ah @ B^T, fp32 accum.
// MODE 0: fp32 C out.
// MODE 1: rope + scale + split-fp16 (hi+lo) out.
// MODE 2: rope + scale + fp16 hi-only out.
// MODE 3: fused K/V: blockIdx.x<8 -> K rows (MODE1 epi); else V (transposed
//         fp16 hi out to Vt = (\_\_half*)C; B matrix taken from Al slot).
// 128x128 tile, k32, 3-stage cp.async ring, 256 threads, 2 CTAs/SM.
// ---------------------------------------------------------------------------
#define HGEMM_SMEM (3 * 32768)

template<int MODE>
__global__ __launch_bounds__(256, 2)
void hgemm_split(const __half* __restrict__ Ah, const __half* __restrict__ Al,
                 const __half* __restrict__ Bh,
                 float* __restrict__ C,
                 __half* __restrict__ Hi, __half* __restrict__ Lo,
                 const float* __restrict__ cosw, const float* __restrict__ sinw,
                 float scale, int M, int N, int K) {
    extern __shared__ __half smh[];
    const uint32_t sbase = (uint32_t)__cvta_generic_to_shared(smh);

    const int t    = threadIdx.x;
    const int m0   = blockIdx.y * 128;
    const bool isK = (MODE != 3) || (blockIdx.x < 8);
    const int n0   = (MODE == 3 ? (blockIdx.x & 7) : blockIdx.x) * 128;
    const __half* __restrict__ B = (MODE == 3 && !isK) ? Al : Bh;

    const int warp = t >> 5;
    const int lane = t & 31;
    const int wm   = (warp >> 1) * 32;
    const int wn   = (warp & 1) * 64;

    const int a_mloc = lane & 15;
    const int a_gsel = lane >> 4;
    const int b_nloc = (lane & 7) + ((lane & 16) >> 1);
    const int b_gsel = (lane >> 3) & 1;

    float acc[2][8][4];
#pragma unroll
    for (int mt = 0; mt < 2; mt++)
#pragma unroll
        for (int nt = 0; nt < 8; nt++)
#pragma unroll
            for (int r = 0; r < 4; r++) acc[mt][nt][r] = 0.f;

    auto issue = [&](int k0, int buf) {
        uint32_t abase = sbase + buf * 32768;
        uint32_t bbase = abase + 16384;
#pragma unroll
        for (int i = 0; i < 2; i++) {
            int ga = t + i * 256;
            int m = ga >> 2, sg = ga & 3;
            const __half* src = Ah + (size_t)(m0 + m) * K + k0 + sg * 8;
            cp16(abase + m * 128 + ((sg ^ (m & 7)) << 4), src);
        }
#pragma unroll
        for (int i = 0; i < 2; i++) {
            int ga = t + i * 256;
            int n = ga >> 2, sg = ga & 3;
            const __half* src = B + (size_t)(n0 + n) * K + k0 + sg * 8;
            cp16(bbase + n * 128 + ((sg ^ (n & 7)) << 4), src);
        }
    };

    const int NIT = K >> 5;
    issue(0, 0);
    asm volatile("cp.async.commit_group;");
    issue(32, 1);
    asm volatile("cp.async.commit_group;");

    for (int it = 0; it < NIT; it++) {
        if (it + 2 < NIT) {
            issue((it + 2) << 5, (it + 2) % 3);
            asm volatile("cp.async.commit_group;");
            asm volatile("cp.async.wait_group 2;");
        } else if (it + 1 < NIT) {
            asm volatile("cp.async.wait_group 1;");
        } else {
            asm volatile("cp.async.wait_group 0;");
        }
        __syncthreads();

        const uint32_t abase = sbase + (it % 3) * 32768;
        const uint32_t bbase = abase + 16384;

#pragma unroll
        for (int c = 0; c < 2; c++) {
            uint32_t ah[2][4], bb[4][4];
#pragma unroll
            for (int mt = 0; mt < 2; mt++) {
                int m = wm + mt * 16 + a_mloc;
                int sg = 2 * c + a_gsel;
                LDSM4(ah[mt][0], ah[mt][1], ah[mt][2], ah[mt][3],
                      abase + m * 128 + ((sg ^ (m & 7)) << 4));
            }
#pragma unroll
            for (int p = 0; p < 4; p++) {
                int n = wn + p * 16 + b_nloc;
                int sg = 2 * c + b_gsel;
                LDSM4(bb[p][0], bb[p][1], bb[p][2], bb[p][3],
                      bbase + n * 128 + ((sg ^ (n & 7)) << 4));
            }
#pragma unroll
            for (int mt = 0; mt < 2; mt++)
#pragma unroll
                for (int p = 0; p < 4; p++) {
                    MMA16816(acc[mt][2 * p],     ah[mt], bb[p][0], bb[p][1]);
                    MMA16816(acc[mt][2 * p + 1], ah[mt], bb[p][2], bb[p][3]);
                }
        }
        __syncthreads();
    }

    // ---- epilogue ----
    const bool ropeOut = (MODE == 1) || (MODE == 2) || (MODE == 3 && isK);
#pragma unroll
    for (int mt = 0; mt < 2; mt++) {
        int r = m0 + wm + mt * 16 + (lane >> 2);
#pragma unroll
        for (int nt = 0; nt < 8; nt++) {
            int cc = n0 + wn + nt * 8 + (lane & 3) * 2;
            if (MODE == 0) {
                float* p0 = C + (size_t)r * N + cc;
                p0[0] = acc[mt][nt][0];
                p0[1] = acc[mt][nt][1];
                float* p1 = p0 + 8 * N;
                p1[0] = acc[mt][nt][2];
                p1[1] = acc[mt][nt][3];
            } else if (MODE == 3 && !isK) {
                // transposed fp16 V out: Vt[d][s]
                __half* Vt = (__half*)C;
                Vt[(size_t)cc * S_LEN + r]           = __float2half_rn(acc[mt][nt][0]);
                Vt[(size_t)(cc + 1) * S_LEN + r]     = __float2half_rn(acc[mt][nt][1]);
                Vt[(size_t)cc * S_LEN + r + 8]       = __float2half_rn(acc[mt][nt][2]);
                Vt[(size_t)(cc + 1) * S_LEN + r + 8] = __float2half_rn(acc[mt][nt][3]);
            } else if (ropeOut) {
                int i = (cc & 127) >> 1;
                {
                    float cw = cosw[r * 64 + i], sw = sinw[r * 64 + i];
                    float t0 = acc[mt][nt][0], t1 = acc[mt][nt][1];
                    float r0 = (t0 * cw - t1 * sw) * scale;
                    float r1 = (t0 * sw + t1 * cw) * scale;
                    if (MODE == 2) {
                        *(__half2*)(Hi + (size_t)r * N + cc) =
                            __halves2half2(__float2half_rn(r0), __float2half_rn(r1));
                    } else {
                        __half2 lo2, hi2 = split_pair(r0, r1, lo2);
                        *(__half2*)(Hi + (size_t)r * N + cc) = hi2;
                        *(__half2*)(Lo + (size_t)r * N + cc) = lo2;
                    }
                }
                {
                    int r8 = r + 8;
                    float cw = cosw[r8 * 64 + i], sw = sinw[r8 * 64 + i];
                    float t0 = acc[mt][nt][2], t1 = acc[mt][nt][3];
                    float r0 = (t0 * cw - t1 * sw) * scale;
                    float r1 = (t0 * sw + t1 * cw) * scale;
                    if (MODE == 2) {
                        *(__half2*)(Hi + (size_t)r8 * N + cc) =
                            __halves2half2(__float2half_rn(r0), __float2half_rn(r1));
                    } else {
                        __half2 lo2, hi2 = split_pair(r0, r1, lo2);
                        *(__half2*)(Hi + (size_t)r8 * N + cc) = hi2;
                        *(__half2*)(Lo + (size_t)r8 * N + cc) = lo2;
                    }
                }
            }
        }
    }
}

// ---------------------------------------------------------------------------
// Flash attention: S = Qh·(Kh+Kl), O = Ph·Vh. fp16 out.
// smem: Q(hi) 16KB | K hi+lo 32KB | V hi 16KB = 64KB (up to 3 CTAs/SM).
// ---------------------------------------------------------------------------
#define FQ_OFF  0
#define FK_OFF  16384
#define FV_OFF  49152
#define FLASH_TC_SMEM 65536

__global__ __launch_bounds__(128, 1)
void flash_tc(const __half* __restrict__ Qh,
              const __half* __restrict__ Kh, const __half* __restrict__ Kl,
              const __half* __restrict__ Vth,
              __half* __restrict__ Oh) {
    extern __shared__ char smc[];
    const uint32_t sb = (uint32_t)__cvta_generic_to_shared(smc);
    const int t    = threadIdx.x;
    const int lane = t & 31;
    const int warp = t >> 5;
    const int qt   = (int)gridDim.x - 1 - (int)blockIdx.x;
    const int h    = blockIdx.y;
    const int kh   = h >> 2;
    const int q0   = qt * 64;

    const int a_ml = lane & 15;
    const int a_gs = lane >> 4;
    const int b_nl = (lane & 7) + ((lane & 16) >> 1);
    const int b_gs = (lane >> 3) & 1;

    // Q tile (hi only): 1024 granules, 8 per thread
#pragma unroll
    for (int i = 0; i < 8; i++) {
        int g = t + i * 128;
        int r = g >> 4, c = g & 15;
        const __half* src = Qh + (size_t)(q0 + r) * D_MODEL + h * HDIM + c * 8;
        cp16(sb + FQ_OFF + r * 256 + ((c ^ (r & 7)) << 4), src);
    }
    asm volatile("cp.async.commit_group;");

    float o[16][4];
#pragma unroll
    for (int nt = 0; nt < 16; nt++)
#pragma unroll
        for (int j = 0; j < 4; j++) o[nt][j] = 0.f;
    float m0r = -1e30f, m1r = -1e30f, l0 = 0.f, l1 = 0.f;

    for (int kt = 0; kt <= qt; kt++) {
        const int k0 = kt * 64;
        __syncthreads();
        // K hi+lo: 2048 granules, 16/thread
#pragma unroll
        for (int i = 0; i < 16; i++) {
            int g = t + i * 128;
            int hf = g >> 10, gg = g & 1023;
            int r = gg >> 4, c = gg & 15;
            const __half* src = (hf ? Kl : Kh)
                              + (size_t)(k0 + r) * KV_D + kh * HDIM + c * 8;
            cp16(sb + FK_OFF + hf * 16384 + r * 256 + ((c ^ (r & 7)) << 4), src);
        }
        // V hi: 1024 granules, 8/thread
#pragma unroll
        for (int i = 0; i < 8; i++) {
            int g = t + i * 128;
            int r = g >> 3, c = g & 7;
            const __half* src = Vth + (size_t)(kh * HDIM + r) * S_LEN + k0 + c * 8;
            cp16(sb + FV_OFF + r * 128 + ((c ^ (r & 7)) << 4), src);
        }
        asm volatile("cp.async.commit_group;");
        asm volatile("cp.async.wait_group 0;");
        __syncthreads();

        float sacc[8][4];
#pragma unroll
        for (int nt = 0; nt < 8; nt++)
#pragma unroll
            for (int j = 0; j < 4; j++) sacc[nt][j] = 0.f;

#pragma unroll
        for (int kc = 0; kc < 8; kc++) {
            uint32_t aqh[4];
            {
                int r = warp * 16 + a_ml;
                int cf = 2 * kc + a_gs;
                LDSM4(aqh[0], aqh[1], aqh[2], aqh[3],
                      sb + FQ_OFF + r * 256 + ((cf ^ (r & 7)) << 4));
            }
#pragma unroll
            for (int p = 0; p < 4; p++) {
                int n = p * 16 + b_nl;
                int cf = 2 * kc + b_gs;
                uint32_t ka = sb + FK_OFF + n * 256 + ((cf ^ (n & 7)) << 4);
                uint32_t bh[4], bl[4];
                LDSM4(bh[0], bh[1], bh[2], bh[3], ka);
                LDSM4(bl[0], bl[1], bl[2], bl[3], ka + 16384);
                MMA16816(sacc[2 * p],     aqh, bh[0], bh[1]);
                MMA16816(sacc[2 * p + 1], aqh, bh[2], bh[3]);
                MMA16816(sacc[2 * p],     aqh, bl[0], bl[1]);
                MMA16816(sacc[2 * p + 1], aqh, bl[2], bl[3]);
            }
        }

        if (kt == qt) {
            int rg0 = q0 + warp * 16 + (lane >> 2);
#pragma unroll
            for (int nt = 0; nt < 8; nt++) {
                int cg = k0 + nt * 8 + (lane & 3) * 2;
                if (cg     > rg0)     sacc[nt][0] += -1e9f;
                if (cg + 1 > rg0)     sacc[nt][1] += -1e9f;
                if (cg     > rg0 + 8) sacc[nt][2] += -1e9f;
                if (cg + 1 > rg0 + 8) sacc[nt][3] += -1e9f;
            }
        }

        float rmax0 = -1e30f, rmax1 = -1e30f;
#pragma unroll
        for (int nt = 0; nt < 8; nt++) {
            rmax0 = fmaxf(rmax0, fmaxf(sacc[nt][0], sacc[nt][1]));
            rmax1 = fmaxf(rmax1, fmaxf(sacc[nt][2], sacc[nt][3]));
        }
#pragma unroll
        for (int off = 1; off < 4; off <<= 1) {
            rmax0 = fmaxf(rmax0, __shfl_xor_sync(0xffffffffu, rmax0, off));
            rmax1 = fmaxf(rmax1, __shfl_xor_sync(0xffffffffu, rmax1, off));
        }
        float mn0 = fmaxf(m0r, rmax0), mn1 = fmaxf(m1r, rmax1);
        float al0 = __expf(m0r - mn0), al1 = __expf(m1r - mn1);
        m0r = mn0; m1r = mn1;

        float rs0 = 0.f, rs1 = 0.f;
#pragma unroll
        for (int nt = 0; nt < 8; nt++) {
            sacc[nt][0] = __expf(sacc[nt][0] - mn0);
            sacc[nt][1] = __expf(sacc[nt][1] - mn0);
            sacc[nt][2] = __expf(sacc[nt][2] - mn1);
            sacc[nt][3] = __expf(sacc[nt][3] - mn1);
            rs0 += sacc[nt][0] + sacc[nt][1];
            rs1 += sacc[nt][2] + sacc[nt][3];
        }
#pragma unroll
        for (int off = 1; off < 4; off <<= 1) {
            rs0 += __shfl_xor_sync(0xffffffffu, rs0, off);
            rs1 += __shfl_xor_sync(0xffffffffu, rs1, off);
        }
        l0 = l0 * al0 + rs0;
        l1 = l1 * al1 + rs1;
#pragma unroll
        for (int nt = 0; nt < 16; nt++) {
            o[nt][0] *= al0; o[nt][1] *= al0;
            o[nt][2] *= al1; o[nt][3] *= al1;
        }

#pragma unroll
        for (int kc = 0; kc < 4; kc++) {
            uint32_t ph[4];
            {
                __half2 h2;
                h2 = __halves2half2(__float2half_rn(sacc[2*kc][0]),
                                    __float2half_rn(sacc[2*kc][1]));
                ph[0] = *(uint32_t*)&h2;
                h2 = __halves2half2(__float2half_rn(sacc[2*kc][2]),
                                    __float2half_rn(sacc[2*kc][3]));
                ph[1] = *(uint32_t*)&h2;
                h2 = __halves2half2(__float2half_rn(sacc[2*kc+1][0]),
                                    __float2half_rn(sacc[2*kc+1][1]));
                ph[2] = *(uint32_t*)&h2;
                h2 = __halves2half2(__float2half_rn(sacc[2*kc+1][2]),
                                    __float2half_rn(sacc[2*kc+1][3]));
                ph[3] = *(uint32_t*)&h2;
            }
#pragma unroll
            for (int p = 0; p < 8; p++) {
                int n = p * 16 + b_nl;
                int cf = 2 * kc + b_gs;
                uint32_t va = sb + FV_OFF + n * 128 + ((cf ^ (n & 7)) << 4);
                uint32_t bh[4];
                LDSM4(bh[0], bh[1], bh[2], bh[3], va);
                MMA16816(o[2 * p],     ph, bh[0], bh[1]);
                MMA16816(o[2 * p + 1], ph, bh[2], bh[3]);
            }
        }
    }

    // ---- epilogue: normalize, fp16 out ----
    float inv0 = 1.f / l0, inv1 = 1.f / l1;
    int rg0 = q0 + warp * 16 + (lane >> 2);
#pragma unroll
    for (int nt = 0; nt < 16; nt++) {
        int col = h * HDIM + nt * 8 + (lane & 3) * 2;
        *(__half2*)(Oh + (size_t)rg0 * D_MODEL + col) =
            __halves2half2(__float2half_rn(o[nt][0] * inv0),
                           __float2half_rn(o[nt][1] * inv0));
        *(__half2*)(Oh + (size_t)(rg0 + 8) * D_MODEL + col) =
            __halves2half2(__float2half_rn(o[nt][2] * inv1),
                           __float2half_rn(o[nt][3] * inv1));
    }
}

// ---------------------------------------------------------------------------
extern "C" void kernel_launch(void* const* d_in, const int* in_sizes, int n_in,
                              void* d_out, int out_size) {
    const float* x  = (const float*)d_in[0];
    const float* fc = (const float*)d_in[1];
    const float* fs = (const float*)d_in[2];
    const float* wq = (const float*)d_in[4];
    const float* wk = (const float*)d_in[5];
    const float* wv = (const float*)d_in[6];
    const float* wo = (const float*)d_in[7];
    float* out = (float*)d_out;

    __half *xh, *wqh, *wkh, *wvh, *woh, *ah;
    __half *qfh, *kfh, *kfl, *vth;
    cudaGetSymbolAddress((void**)&xh,  g_xh);
    cudaGetSymbolAddress((void**)&wqh, g_wqh);
    cudaGetSymbolAddress((void**)&wkh, g_wkh);
    cudaGetSymbolAddress((void**)&wvh, g_wvh);
    cudaGetSymbolAddress((void**)&woh, g_woh);
    cudaGetSymbolAddress((void**)&ah,  g_ah);
    cudaGetSymbolAddress((void**)&qfh, g_Qfh);
    cudaGetSymbolAddress((void**)&kfh, g_Kfh); cudaGetSymbolAddress((void**)&kfl, g_Kfl);
    cudaGetSymbolAddress((void**)&vth, g_Vth);

    cudaFuncSetAttribute((const void*)hgemm_split<0>,
                         cudaFuncAttributeMaxDynamicSharedMemorySize, HGEMM_SMEM);
    cudaFuncSetAttribute((const void*)hgemm_split<2>,
                         cudaFuncAttributeMaxDynamicSharedMemorySize, HGEMM_SMEM);
    cudaFuncSetAttribute((const void*)hgemm_split<3>,
                         cudaFuncAttributeMaxDynamicSharedMemorySize, HGEMM_SMEM);
    cudaFuncSetAttribute((const void*)flash_tc,
                         cudaFuncAttributeMaxDynamicSharedMemorySize, FLASH_TC_SMEM);

    const int NW4 = D_MODEL * D_MODEL / 4;

    // one vectorized conversion launch for x + all weights
    cvt_all<<<(NW4 + 255) / 256, 256>>>(x, wq, wk, wv, wo,
                                        xh, wqh, wkh, wvh, woh);

    // Q projection: rope+scale, fp16 hi-only out
    hgemm_split<2><<<dim3(32, 16), 256, HGEMM_SMEM>>>(
        xh, nullptr, wqh, nullptr, qfh, nullptr, fc, fs, ATT_SCALE,
        S_LEN, NH * HDIM, D_MODEL);

    // fused K (rope, split hi+lo) + V (transposed fp16) projections
    hgemm_split<3><<<dim3(16, 16), 256, HGEMM_SMEM>>>(
        xh, wvh, wkh, (float*)vth, kfh, kfl, fc, fs, 1.f,
        S_LEN, KV_D, D_MODEL);

    // Flash attention (QK 2-term, PV 1-term), fp16 out
    flash_tc<<<dim3(32, 32), 128, FLASH_TC_SMEM>>>(qfh, kfh, kfl, vth, ah);

    // Output projection (1-term), fp32 out
    hgemm_split<0><<<dim3(32, 16), 256, HGEMM_SMEM>>>(
        ah, nullptr, woh, out, nullptr, nullptr, nullptr, nullptr, 1.f,
        S_LEN, D_MODEL, D_MODEL);
}